// round 4
// baseline (speedup 1.0000x reference)
#include <cuda_runtime.h>
#include <cstdint>

#define Bn   8
#define Cc   256
#define HWn  4096
#define CPG  32
#define PA   20    // smem pitch for qkv/proj [128 rows][16 k] tiles

// flash smem pitches (floats)
#define QP  260
#define KP2 132
#define VP  264
#define PP  68
// flash smem layout (float offsets)
#define OFF_Q   0
#define OFF_KA  (OFF_Q  + 64*QP)      // 16640
#define OFF_KB  (OFF_KA + 64*KP2)     // 25088
#define OFF_V0  (OFF_KB + 64*KP2)     // 33536
#define OFF_V1  (OFF_V0 + 32*VP)      // 41984
#define OFF_P   (OFF_V1 + 32*VP)      // 50432
#define OFF_RM  (OFF_P  + 64*PP)      // 54784
#define OFF_RS  (OFF_RM + 256)        // 55040
#define SMEM_FLOATS (OFF_RS + 256)    // 55296
#define SMEM_BYTES  (SMEM_FLOATS * 4) // 221184 B

// ---------------- scratch -----------------------------------------------------
__device__ float g_xn[(size_t)Bn * HWn * Cc];
__device__ float g_q [(size_t)Bn * HWn * Cc];
__device__ float g_k [(size_t)Bn * HWn * Cc];
__device__ float g_v [(size_t)Bn * HWn * Cc];
__device__ float g_ao[(size_t)Bn * HWn * Cc];

// ---------------- helpers ------------------------------------------------------
__device__ __forceinline__ float tf32r(float x) {
    uint32_t r;
    asm("cvt.rna.tf32.f32 %0, %1;" : "=r"(r) : "f"(x));
    return __uint_as_float(r);
}
__device__ __forceinline__ float4 tf32r4(float4 v) {
    float4 o; o.x = tf32r(v.x); o.y = tf32r(v.y); o.z = tf32r(v.z); o.w = tf32r(v.w);
    return o;
}
__device__ __forceinline__ void mma8(float c[4], uint32_t a0, uint32_t a1, uint32_t a2,
                                     uint32_t a3, uint32_t b0, uint32_t b1) {
    asm("mma.sync.aligned.m16n8k8.row.col.f32.tf32.tf32.f32 "
        "{%0,%1,%2,%3},{%4,%5,%6,%7},{%8,%9},{%0,%1,%2,%3};"
        : "+f"(c[0]), "+f"(c[1]), "+f"(c[2]), "+f"(c[3])
        : "r"(a0), "r"(a1), "r"(a2), "r"(a3), "r"(b0), "r"(b1));
}
#define U(x) __float_as_uint(x)

__device__ __forceinline__ void cp16(float* dst, const float* src) {
    uint32_t d = (uint32_t)__cvta_generic_to_shared(dst);
    asm volatile("cp.async.cg.shared.global [%0], [%1], 16;\n" :: "r"(d), "l"(src));
}
__device__ __forceinline__ void cpcommit() { asm volatile("cp.async.commit_group;\n"); }
template<int N> __device__ __forceinline__ void cpwait() {
    asm volatile("cp.async.wait_group %0;\n" :: "n"(N));
}

// ---------------- GroupNorm ----------------------------------------------------
__global__ __launch_bounds__(512) void gn_kernel(const float* __restrict__ x,
                                                 const float* __restrict__ w,
                                                 const float* __restrict__ bv) {
    int bg = blockIdx.x;
    int b = bg >> 3, g = bg & 7;
    const float* xb = x + ((size_t)b * Cc + (size_t)g * CPG) * HWn;
    const int NEL = CPG * HWn;

    float s = 0.f, ss = 0.f;
    for (int i = threadIdx.x; i < NEL; i += blockDim.x) {
        float v = xb[i];
        s += v; ss += v * v;
    }
    __shared__ float rs[32], rss[32];
    #pragma unroll
    for (int o = 16; o; o >>= 1) {
        s  += __shfl_down_sync(0xffffffffu, s, o);
        ss += __shfl_down_sync(0xffffffffu, ss, o);
    }
    int lane = threadIdx.x & 31, wid = threadIdx.x >> 5;
    if (lane == 0) { rs[wid] = s; rss[wid] = ss; }
    __syncthreads();
    if (wid == 0) {
        s  = (lane < 16) ? rs[lane]  : 0.f;
        ss = (lane < 16) ? rss[lane] : 0.f;
        #pragma unroll
        for (int o = 16; o; o >>= 1) {
            s  += __shfl_down_sync(0xffffffffu, s, o);
            ss += __shfl_down_sync(0xffffffffu, ss, o);
        }
        if (lane == 0) { rs[0] = s; rss[0] = ss; }
    }
    __syncthreads();
    float mean = rs[0] / (float)NEL;
    float var  = rss[0] / (float)NEL - mean * mean;
    float rstd = rsqrtf(var + 1e-5f);

    float* out = g_xn + (size_t)b * HWn * Cc + (size_t)g * CPG;
    for (int i = threadIdx.x; i < NEL; i += blockDim.x) {
        int c = i & 31;
        int p = i >> 5;
        float v = xb[(size_t)c * HWn + p];
        out[(size_t)p * Cc + c] = (v - mean) * rstd * w[g * CPG + c] + bv[g * CPG + c];
    }
}

// ---------------- shared NT GEMM mainloop (qkv / proj) --------------------------
__device__ __forceinline__ void gemm_nt(const float* __restrict__ Ag,
                                        const float* __restrict__ Bg,
                                        int K, int lda, int ldb,
                                        float* As, float* Bs,
                                        float acc[2][8][4]) {
    int t = threadIdx.x;
    int r = t >> 1, cc = (t & 1) * 8;
    int wid = t >> 5, lane = t & 31, g = lane >> 2, t4 = lane & 3;
    int wm = (wid >> 1) * 32, wn = (wid & 1) * 64;

    #pragma unroll 1
    for (int kb = 0; kb < K; kb += 16) {
        float4 av0 = *(const float4*)(Ag + (size_t)r * lda + kb + cc);
        float4 av1 = *(const float4*)(Ag + (size_t)r * lda + kb + cc + 4);
        float4 bv0 = *(const float4*)(Bg + (size_t)r * ldb + kb + cc);
        float4 bv1 = *(const float4*)(Bg + (size_t)r * ldb + kb + cc + 4);
        __syncthreads();
        *(float4*)&As[r * PA + cc]     = tf32r4(av0);
        *(float4*)&As[r * PA + cc + 4] = tf32r4(av1);
        *(float4*)&Bs[r * PA + cc]     = tf32r4(bv0);
        *(float4*)&Bs[r * PA + cc + 4] = tf32r4(bv1);
        __syncthreads();
        #pragma unroll
        for (int ks = 0; ks < 16; ks += 8) {
            uint32_t af[2][4];
            #pragma unroll
            for (int mt = 0; mt < 2; mt++) {
                int row = (wm + mt * 16 + g) * PA + ks + t4;
                af[mt][0] = U(As[row]);
                af[mt][1] = U(As[row + 8 * PA]);
                af[mt][2] = U(As[row + 4]);
                af[mt][3] = U(As[row + 8 * PA + 4]);
            }
            uint32_t bf[8][2];
            #pragma unroll
            for (int nt = 0; nt < 8; nt++) {
                int row = (wn + nt * 8 + g) * PA + ks + t4;
                bf[nt][0] = U(Bs[row]);
                bf[nt][1] = U(Bs[row + 4]);
            }
            #pragma unroll
            for (int mt = 0; mt < 2; mt++)
                #pragma unroll
                for (int nt = 0; nt < 8; nt++)
                    mma8(acc[mt][nt], af[mt][0], af[mt][1], af[mt][2], af[mt][3],
                         bf[nt][0], bf[nt][1]);
        }
    }
}

// ---------------- QKV GEMM -------------------------------------------------------
__global__ __launch_bounds__(256) void qkv_kernel(const float* __restrict__ W,
                                                  const float* __restrict__ bias) {
    __shared__ float As[128 * PA];
    __shared__ float Bs[128 * PA];
    int b = blockIdx.z;
    int pm = blockIdx.y * 128;
    int on = blockIdx.x * 128;
    const float* Ag = g_xn + (size_t)b * HWn * Cc + (size_t)pm * Cc;
    const float* Bg = W + (size_t)on * Cc;

    float acc[2][8][4] = {};
    gemm_nt(Ag, Bg, Cc, Cc, Cc, As, Bs, acc);

    int t = threadIdx.x, wid = t >> 5, lane = t & 31, g = lane >> 2, t4 = lane & 3;
    int wm = (wid >> 1) * 32, wn = (wid & 1) * 64;
    float* dst = (on < 256) ? g_q : (on < 512) ? g_k : g_v;
    int obase = on & 255;
    dst += (size_t)b * HWn * Cc;

    #pragma unroll
    for (int nt = 0; nt < 8; nt++) {
        int ocol = wn + nt * 8 + t4 * 2;
        float2 bb = *(const float2*)&bias[on + ocol];
        #pragma unroll
        for (int mt = 0; mt < 2; mt++) {
            int p0 = pm + wm + mt * 16 + g;
            float2 v0 = { acc[mt][nt][0] + bb.x, acc[mt][nt][1] + bb.y };
            float2 v1 = { acc[mt][nt][2] + bb.x, acc[mt][nt][3] + bb.y };
            *(float2*)&dst[(size_t)p0 * Cc + obase + ocol]       = v0;
            *(float2*)&dst[(size_t)(p0 + 8) * Cc + obase + ocol] = v1;
        }
    }
}

// ---------------- flash attention (512 threads, 128-wide K halves) --------------
__device__ __forceinline__ void copyK(const float* Kg, int kt, int half, float* kb, int t) {
    const float* src = Kg + (size_t)(kt * 64) * Cc + half * 128;
    #pragma unroll
    for (int i = 0; i < 4; i++) {
        int idx = t + 512 * i;
        int row = idx >> 5, c4 = (idx & 31) * 4;
        cp16(kb + row * KP2 + c4, src + (size_t)row * Cc + c4);
    }
}
__device__ __forceinline__ void copyV(const float* Vg, int kt, int half, float* vb, int t) {
    const float* src = Vg + (size_t)(kt * 64 + half * 32) * Cc;
    #pragma unroll
    for (int i = 0; i < 4; i++) {
        int idx = t + 512 * i;
        int row = idx >> 6, c4 = (idx & 63) * 4;
        cp16(vb + row * VP + c4, src + (size_t)row * Cc + c4);
    }
}
__device__ __forceinline__ void mmaS2(const float* Qs, const float* kb, float sacc[2][4],
                                      int h, int qr0, int wm, int g, int t4) {
    #pragma unroll
    for (int ks = 0; ks < 128; ks += 8) {
        int kq = h * 128 + ks;
        uint32_t a0 = U(Qs[qr0 * QP + kq + t4]);
        uint32_t a1 = U(Qs[(qr0 + 8) * QP + kq + t4]);
        uint32_t a2 = U(Qs[qr0 * QP + kq + t4 + 4]);
        uint32_t a3 = U(Qs[(qr0 + 8) * QP + kq + t4 + 4]);
        #pragma unroll
        for (int nt = 0; nt < 2; nt++) {
            int r = wm * 16 + nt * 8 + g;
            uint32_t b0 = U(kb[r * KP2 + ks + t4]);
            uint32_t b1 = U(kb[r * KP2 + ks + t4 + 4]);
            mma8(sacc[nt], a0, a1, a2, a3, b0, b1);
        }
    }
}

__global__ void __launch_bounds__(512, 1) flash_kernel() {
    extern __shared__ float sm[];
    float* Qs = sm + OFF_Q;
    float* KA = sm + OFF_KA;
    float* KB = sm + OFF_KB;
    float* V0 = sm + OFF_V0;
    float* V1 = sm + OFF_V1;
    float* Ps = sm + OFF_P;
    float* RM = sm + OFF_RM;   // [4][64]
    float* RS = sm + OFF_RS;   // [4][64]

    int b = blockIdx.y;
    int qbase = blockIdx.x * 64;
    size_t bo = (size_t)b * HWn * Cc;
    const float* Qg = g_q + bo + (size_t)qbase * Cc;
    const float* Kg = g_k + bo;
    const float* Vg = g_v + bo;

    int t = threadIdx.x;
    int wid = t >> 5, lane = t & 31, g = lane >> 2, t4 = lane & 3;
    int wq = wid >> 2, wm = wid & 3;     // S: 4q x 4m; PV: 4q x 4c (wm as wc)
    int qr0 = wq * 16 + g, qr1 = qr0 + 8;

    float oacc[8][4] = {};
    float M0 = -1e30f, M1 = -1e30f, L0 = 0.f, L1 = 0.f;

    // prologue: queue = [KA0, V0_0, KB0, V1_0]
    copyK(Kg, 0, 0, KA, t); cpcommit();
    copyV(Vg, 0, 0, V0, t); cpcommit();
    copyK(Kg, 0, 1, KB, t); cpcommit();
    copyV(Vg, 0, 1, V1, t); cpcommit();

    // Q tile: load + tf32 round into smem
    #pragma unroll
    for (int i = 0; i < 8; i++) {
        int idx = t + 512 * i;
        int row = idx >> 6, c4 = (idx & 63) * 4;
        float4 v = *(const float4*)(Qg + (size_t)row * Cc + c4);
        *(float4*)&Qs[row * QP + c4] = tf32r4(v);
    }

    for (int kt = 0; kt < 64; kt++) {
        float sacc[2][4] = {};
        cpwait<3>(); __syncthreads();          // KA(kt) visible
        mmaS2(Qs, KA, sacc, 0, qr0, wm, g, t4);
        cpwait<1>(); __syncthreads();          // KB(kt), V0(kt) visible
        mmaS2(Qs, KB, sacc, 1, qr0, wm, g, t4);
        __syncthreads();                        // KA/KB consumed by all
        if (kt < 63) {
            copyK(Kg, kt + 1, 0, KA, t); cpcommit();
            copyK(Kg, kt + 1, 1, KB, t); cpcommit();
            cpwait<2>();                        // V1(kt) done
        } else {
            cpwait<0>();
        }

        // ---- online softmax (log2 domain; SCL = log2(e)/16) ----
        const float SCL = 0.090169311f;
        float mx0 = -1e30f, mx1 = -1e30f;
        #pragma unroll
        for (int nt = 0; nt < 2; nt++) {
            #pragma unroll
            for (int j = 0; j < 4; j++) sacc[nt][j] *= SCL;
            mx0 = fmaxf(mx0, fmaxf(sacc[nt][0], sacc[nt][1]));
            mx1 = fmaxf(mx1, fmaxf(sacc[nt][2], sacc[nt][3]));
        }
        mx0 = fmaxf(mx0, __shfl_xor_sync(0xffffffffu, mx0, 1));
        mx0 = fmaxf(mx0, __shfl_xor_sync(0xffffffffu, mx0, 2));
        mx1 = fmaxf(mx1, __shfl_xor_sync(0xffffffffu, mx1, 1));
        mx1 = fmaxf(mx1, __shfl_xor_sync(0xffffffffu, mx1, 2));
        if (t4 == 0) { RM[wm * 64 + qr0] = mx0; RM[wm * 64 + qr1] = mx1; }
        __syncthreads();                        // RM published; V1 visible
        float tm0 = fmaxf(fmaxf(RM[qr0], RM[64 + qr0]),
                          fmaxf(RM[128 + qr0], RM[192 + qr0]));
        float tm1 = fmaxf(fmaxf(RM[qr1], RM[64 + qr1]),
                          fmaxf(RM[128 + qr1], RM[192 + qr1]));
        float Mn0 = fmaxf(M0, tm0), Mn1 = fmaxf(M1, tm1);
        float f0 = exp2f(M0 - Mn0), f1 = exp2f(M1 - Mn1);
        M0 = Mn0; M1 = Mn1;
        float s0 = 0.f, s1 = 0.f;
        #pragma unroll
        for (int nt = 0; nt < 2; nt++) {
            float p00 = exp2f(sacc[nt][0] - Mn0);
            float p01 = exp2f(sacc[nt][1] - Mn0);
            float p10 = exp2f(sacc[nt][2] - Mn1);
            float p11 = exp2f(sacc[nt][3] - Mn1);
            s0 += p00 + p01; s1 += p10 + p11;
            int c = wm * 16 + nt * 8 + t4 * 2;
            float2 u0 = { tf32r(p00), tf32r(p01) };
            float2 u1 = { tf32r(p10), tf32r(p11) };
            *(float2*)&Ps[qr0 * PP + c] = u0;
            *(float2*)&Ps[qr1 * PP + c] = u1;
        }
        s0 += __shfl_xor_sync(0xffffffffu, s0, 1);
        s0 += __shfl_xor_sync(0xffffffffu, s0, 2);
        s1 += __shfl_xor_sync(0xffffffffu, s1, 1);
        s1 += __shfl_xor_sync(0xffffffffu, s1, 2);
        if (t4 == 0) { RS[wm * 64 + qr0] = s0; RS[wm * 64 + qr1] = s1; }
        __syncthreads();                        // Ps + RS published
        L0 = L0 * f0 + RS[qr0] + RS[64 + qr0] + RS[128 + qr0] + RS[192 + qr0];
        L1 = L1 * f1 + RS[qr1] + RS[64 + qr1] + RS[128 + qr1] + RS[192 + qr1];
        #pragma unroll
        for (int nt2 = 0; nt2 < 8; nt2++) {
            oacc[nt2][0] *= f0; oacc[nt2][1] *= f0;
            oacc[nt2][2] *= f1; oacc[nt2][3] *= f1;
        }

        // ---- PV: oacc += P[64x64] @ V[64x256] ----
        #pragma unroll
        for (int m8 = 0; m8 < 64; m8 += 8) {
            const float* V = (m8 < 32) ? V0 : V1;
            int lm = m8 & 31;
            uint32_t a0 = U(Ps[qr0 * PP + m8 + t4]);
            uint32_t a1 = U(Ps[qr1 * PP + m8 + t4]);
            uint32_t a2 = U(Ps[qr0 * PP + m8 + t4 + 4]);
            uint32_t a3 = U(Ps[qr1 * PP + m8 + t4 + 4]);
            #pragma unroll
            for (int nt2 = 0; nt2 < 8; nt2++) {
                int c = wm * 64 + nt2 * 8 + g;
                uint32_t b0 = U(V[(lm + t4) * VP + c]);
                uint32_t b1 = U(V[(lm + t4 + 4) * VP + c]);
                mma8(oacc[nt2], a0, a1, a2, a3, b0, b1);
            }
        }
        __syncthreads();                        // V0/V1/Ps consumed
        if (kt < 63) {
            copyV(Vg, kt + 1, 0, V0, t); cpcommit();
            copyV(Vg, kt + 1, 1, V1, t); cpcommit();
        }
    }

    float r0 = 1.0f / L0, r1 = 1.0f / L1;
    float* AO = g_ao + bo;
    int row0 = qbase + qr0;
    #pragma unroll
    for (int nt2 = 0; nt2 < 8; nt2++) {
        int c = wm * 64 + nt2 * 8 + t4 * 2;
        float2 v0 = { oacc[nt2][0] * r0, oacc[nt2][1] * r0 };
        float2 v1 = { oacc[nt2][2] * r1, oacc[nt2][3] * r1 };
        *(float2*)&AO[(size_t)row0 * Cc + c]       = v0;
        *(float2*)&AO[(size_t)(row0 + 8) * Cc + c] = v1;
    }
}

// ---------------- proj GEMM + residual -------------------------------------------
__global__ __launch_bounds__(256) void proj_kernel(const float* __restrict__ x,
                                                   const float* __restrict__ W,
                                                   const float* __restrict__ pb,
                                                   float* __restrict__ out) {
    __shared__ float As[128 * PA];
    __shared__ float Bs[128 * PA];
    int b = blockIdx.z;
    int om = blockIdx.y * 128;
    int pn = blockIdx.x * 128;
    const float* Ag = W + (size_t)om * Cc;
    const float* Bg = g_ao + (size_t)b * HWn * Cc + (size_t)pn * Cc;

    float acc[2][8][4] = {};
    gemm_nt(Ag, Bg, Cc, Cc, Cc, As, Bs, acc);

    int t = threadIdx.x, wid = t >> 5, lane = t & 31, g = lane >> 2, t4 = lane & 3;
    int wm = (wid >> 1) * 32, wn = (wid & 1) * 64;

    #pragma unroll
    for (int mt = 0; mt < 2; mt++) {
        int o0 = om + wm + mt * 16 + g;
        float b0 = pb[o0], b1 = pb[o0 + 8];
        #pragma unroll
        for (int nt = 0; nt < 8; nt++) {
            int p0 = pn + wn + nt * 8 + t4 * 2;
            size_t off0 = ((size_t)b * Cc + o0) * HWn + p0;
            size_t off1 = ((size_t)b * Cc + o0 + 8) * HWn + p0;
            float2 x0 = *(const float2*)&x[off0];
            float2 x1 = *(const float2*)&x[off1];
            float2 v0 = { acc[mt][nt][0] + b0 + x0.x, acc[mt][nt][1] + b0 + x0.y };
            float2 v1 = { acc[mt][nt][2] + b1 + x1.x, acc[mt][nt][3] + b1 + x1.y };
            *(float2*)&out[off0] = v0;
            *(float2*)&out[off1] = v1;
        }
    }
}

// ---------------- launch ---------------------------------------------------------
extern "C" void kernel_launch(void* const* d_in, const int* in_sizes, int n_in,
                              void* d_out, int out_size) {
    const float* x  = (const float*)d_in[0];
    const float* nw = (const float*)d_in[1];
    const float* nb = (const float*)d_in[2];
    const float* qw = (const float*)d_in[3];
    const float* qb = (const float*)d_in[4];
    const float* pw = (const float*)d_in[5];
    const float* pb = (const float*)d_in[6];
    float* out = (float*)d_out;

    cudaFuncSetAttribute(flash_kernel, cudaFuncAttributeMaxDynamicSharedMemorySize,
                         SMEM_BYTES);

    gn_kernel<<<Bn * 8, 512>>>(x, nw, nb);
    qkv_kernel<<<dim3(6, 32, 8), 256>>>(qw, qb);
    flash_kernel<<<dim3(64, 8), 512, SMEM_BYTES>>>();
    proj_kernel<<<dim3(32, 2, 8), 256>>>(x, pw, pb, out);
}

// round 6
// speedup vs baseline: 1.4623x; 1.4623x over previous
#include <cuda_runtime.h>
#include <cuda_fp16.h>
#include <cstdint>

#define Bn   8
#define Cc   256
#define HWn  4096
#define CPG  32
#define PA   20

// flash smem pitches (half2 units)
#define QP2  132   // 256-half rows (Q, K)
#define VP2  36    // 64-half rows (Vt)
#define PP2  36    // 64-half rows (P)
// flash smem layout (half offsets)
#define OFF_Q   0
#define OFF_K0  16896                 // 64*264
#define OFF_K1  (OFF_K0 + 16896)
#define OFF_VT0 (OFF_K1 + 16896)      // 50688; each 256*72=18432
#define OFF_VT1 (OFF_VT0 + 18432)
#define OFF_P   (OFF_VT1 + 18432)     // 87552; 64*72=4608
#define HALFS_TOTAL (OFF_P + 4608)    // 92160
#define SMEM_BYTES (HALFS_TOTAL * 2 + 1024)   // + RM/RS floats = 185344

// ---------------- scratch -----------------------------------------------------
__device__ float  g_xn[(size_t)Bn * HWn * Cc];
__device__ __half g_q [(size_t)Bn * HWn * Cc];   // token-major [b][p][c]
__device__ __half g_k [(size_t)Bn * HWn * Cc];   // token-major [b][p][c]
__device__ __half g_vt[(size_t)Bn * Cc * HWn];   // channel-major [b][c][m]
__device__ float  g_ao[(size_t)Bn * HWn * Cc];

// ---------------- helpers ------------------------------------------------------
__device__ __forceinline__ float tf32r(float x) {
    uint32_t r;
    asm("cvt.rna.tf32.f32 %0, %1;" : "=r"(r) : "f"(x));
    return __uint_as_float(r);
}
__device__ __forceinline__ float4 tf32r4(float4 v) {
    float4 o; o.x = tf32r(v.x); o.y = tf32r(v.y); o.z = tf32r(v.z); o.w = tf32r(v.w);
    return o;
}
__device__ __forceinline__ void mma8(float c[4], uint32_t a0, uint32_t a1, uint32_t a2,
                                     uint32_t a3, uint32_t b0, uint32_t b1) {
    asm("mma.sync.aligned.m16n8k8.row.col.f32.tf32.tf32.f32 "
        "{%0,%1,%2,%3},{%4,%5,%6,%7},{%8,%9},{%0,%1,%2,%3};"
        : "+f"(c[0]), "+f"(c[1]), "+f"(c[2]), "+f"(c[3])
        : "r"(a0), "r"(a1), "r"(a2), "r"(a3), "r"(b0), "r"(b1));
}
__device__ __forceinline__ void mma16(float c[4], uint32_t a0, uint32_t a1, uint32_t a2,
                                      uint32_t a3, uint32_t b0, uint32_t b1) {
    asm("mma.sync.aligned.m16n8k16.row.col.f32.f16.f16.f32 "
        "{%0,%1,%2,%3},{%4,%5,%6,%7},{%8,%9},{%0,%1,%2,%3};"
        : "+f"(c[0]), "+f"(c[1]), "+f"(c[2]), "+f"(c[3])
        : "r"(a0), "r"(a1), "r"(a2), "r"(a3), "r"(b0), "r"(b1));
}
#define U(x) __float_as_uint(x)
#define H2U(x) (*(const uint32_t*)&(x))

__device__ __forceinline__ void cp16(void* dst, const void* src) {
    uint32_t d = (uint32_t)__cvta_generic_to_shared(dst);
    asm volatile("cp.async.cg.shared.global [%0], [%1], 16;\n" :: "r"(d), "l"(src));
}
__device__ __forceinline__ void cpcommit() { asm volatile("cp.async.commit_group;\n"); }
template<int N> __device__ __forceinline__ void cpwait() {
    asm volatile("cp.async.wait_group %0;\n" :: "n"(N));
}

// ---------------- GroupNorm ----------------------------------------------------
__global__ __launch_bounds__(512) void gn_kernel(const float* __restrict__ x,
                                                 const float* __restrict__ w,
                                                 const float* __restrict__ bv) {
    int bg = blockIdx.x;
    int b = bg >> 3, g = bg & 7;
    const float* xb = x + ((size_t)b * Cc + (size_t)g * CPG) * HWn;
    const int NEL = CPG * HWn;

    float s = 0.f, ss = 0.f;
    for (int i = threadIdx.x; i < NEL; i += blockDim.x) {
        float v = xb[i];
        s += v; ss += v * v;
    }
    __shared__ float rs[32], rss[32];
    #pragma unroll
    for (int o = 16; o; o >>= 1) {
        s  += __shfl_down_sync(0xffffffffu, s, o);
        ss += __shfl_down_sync(0xffffffffu, ss, o);
    }
    int lane = threadIdx.x & 31, wid = threadIdx.x >> 5;
    if (lane == 0) { rs[wid] = s; rss[wid] = ss; }
    __syncthreads();
    if (wid == 0) {
        s  = (lane < 16) ? rs[lane]  : 0.f;
        ss = (lane < 16) ? rss[lane] : 0.f;
        #pragma unroll
        for (int o = 16; o; o >>= 1) {
            s  += __shfl_down_sync(0xffffffffu, s, o);
            ss += __shfl_down_sync(0xffffffffu, ss, o);
        }
        if (lane == 0) { rs[0] = s; rss[0] = ss; }
    }
    __syncthreads();
    float mean = rs[0] / (float)NEL;
    float var  = rss[0] / (float)NEL - mean * mean;
    float rstd = rsqrtf(var + 1e-5f);

    float* out = g_xn + (size_t)b * HWn * Cc + (size_t)g * CPG;
    for (int i = threadIdx.x; i < NEL; i += blockDim.x) {
        int c = i & 31;
        int p = i >> 5;
        float v = xb[(size_t)c * HWn + p];
        out[(size_t)p * Cc + c] = (v - mean) * rstd * w[g * CPG + c] + bv[g * CPG + c];
    }
}

// ---------------- tf32 NT mainloop (qkv / proj) ----------------------------------
__device__ __forceinline__ void gemm_nt(const float* __restrict__ Ag,
                                        const float* __restrict__ Bg,
                                        int K, int lda, int ldb,
                                        float* As, float* Bs,
                                        float acc[2][8][4]) {
    int t = threadIdx.x;
    int r = t >> 1, cc = (t & 1) * 8;
    int wid = t >> 5, lane = t & 31, g = lane >> 2, t4 = lane & 3;
    int wm = (wid >> 1) * 32, wn = (wid & 1) * 64;

    #pragma unroll 1
    for (int kb = 0; kb < K; kb += 16) {
        float4 av0 = *(const float4*)(Ag + (size_t)r * lda + kb + cc);
        float4 av1 = *(const float4*)(Ag + (size_t)r * lda + kb + cc + 4);
        float4 bv0 = *(const float4*)(Bg + (size_t)r * ldb + kb + cc);
        float4 bv1 = *(const float4*)(Bg + (size_t)r * ldb + kb + cc + 4);
        __syncthreads();
        *(float4*)&As[r * PA + cc]     = tf32r4(av0);
        *(float4*)&As[r * PA + cc + 4] = tf32r4(av1);
        *(float4*)&Bs[r * PA + cc]     = tf32r4(bv0);
        *(float4*)&Bs[r * PA + cc + 4] = tf32r4(bv1);
        __syncthreads();
        #pragma unroll
        for (int ks = 0; ks < 16; ks += 8) {
            uint32_t af[2][4];
            #pragma unroll
            for (int mt = 0; mt < 2; mt++) {
                int row = (wm + mt * 16 + g) * PA + ks + t4;
                af[mt][0] = U(As[row]);
                af[mt][1] = U(As[row + 8 * PA]);
                af[mt][2] = U(As[row + 4]);
                af[mt][3] = U(As[row + 8 * PA + 4]);
            }
            uint32_t bf[8][2];
            #pragma unroll
            for (int nt = 0; nt < 8; nt++) {
                int row = (wn + nt * 8 + g) * PA + ks + t4;
                bf[nt][0] = U(Bs[row]);
                bf[nt][1] = U(Bs[row + 4]);
            }
            #pragma unroll
            for (int mt = 0; mt < 2; mt++)
                #pragma unroll
                for (int nt = 0; nt < 8; nt++)
                    mma8(acc[mt][nt], af[mt][0], af[mt][1], af[mt][2], af[mt][3],
                         bf[nt][0], bf[nt][1]);
        }
    }
}

// ---------------- QKV GEMM: q,k fp16 token-major; v fp16 channel-major ----------
__global__ __launch_bounds__(256) void qkv_kernel(const float* __restrict__ W,
                                                  const float* __restrict__ bias) {
    __shared__ float As[128 * PA];
    __shared__ float Bs[128 * PA];
    int b = blockIdx.z;
    int pm = blockIdx.y * 128;
    int on = blockIdx.x * 128;
    const float* Ag = g_xn + (size_t)b * HWn * Cc + (size_t)pm * Cc;
    const float* Bg = W + (size_t)on * Cc;

    float acc[2][8][4] = {};
    gemm_nt(Ag, Bg, Cc, Cc, Cc, As, Bs, acc);

    int t = threadIdx.x, wid = t >> 5, lane = t & 31, g = lane >> 2, t4 = lane & 3;
    int wm = (wid >> 1) * 32, wn = (wid & 1) * 64;

    if (on < 512) {
        __half* dst = ((on < 256) ? g_q : g_k) + (size_t)b * HWn * Cc;
        int obase = on & 255;
        #pragma unroll
        for (int nt = 0; nt < 8; nt++) {
            int ocol = wn + nt * 8 + t4 * 2;
            float2 bb = *(const float2*)&bias[on + ocol];
            #pragma unroll
            for (int mt = 0; mt < 2; mt++) {
                int p0 = pm + wm + mt * 16 + g;
                __half2 v0 = __floats2half2_rn(acc[mt][nt][0] + bb.x, acc[mt][nt][1] + bb.y);
                __half2 v1 = __floats2half2_rn(acc[mt][nt][2] + bb.x, acc[mt][nt][3] + bb.y);
                *(__half2*)&dst[(size_t)p0 * Cc + obase + ocol]       = v0;
                *(__half2*)&dst[(size_t)(p0 + 8) * Cc + obase + ocol] = v1;
            }
        }
    } else {
        __half* dst = g_vt + (size_t)b * Cc * HWn;
        #pragma unroll
        for (int nt = 0; nt < 8; nt++) {
            int ocol = wn + nt * 8 + t4 * 2;
            int c0 = (on - 512) + ocol;
            float2 bb = *(const float2*)&bias[on + ocol];
            #pragma unroll
            for (int mt = 0; mt < 2; mt++) {
                int p0 = pm + wm + mt * 16 + g;
                dst[(size_t)c0 * HWn + p0]           = __float2half(acc[mt][nt][0] + bb.x);
                dst[(size_t)(c0 + 1) * HWn + p0]     = __float2half(acc[mt][nt][1] + bb.y);
                dst[(size_t)c0 * HWn + p0 + 8]       = __float2half(acc[mt][nt][2] + bb.x);
                dst[(size_t)(c0 + 1) * HWn + p0 + 8] = __float2half(acc[mt][nt][3] + bb.y);
            }
        }
    }
}

// ---------------- flash attention (fp16 datapath) --------------------------------
__device__ __forceinline__ void copyK16(const __half* Kg, int kt, __half* kb, int t) {
    // 64 rows x 256 halves (512B = 32 pieces)
    #pragma unroll
    for (int i = 0; i < 8; i++) {
        int idx = t + 256 * i;
        int row = idx >> 5, pc = idx & 31;
        cp16(kb + row * 264 + pc * 8, Kg + (size_t)(kt * 64 + row) * Cc + pc * 8);
    }
}
__device__ __forceinline__ void copyV16(const __half* Vtg, int kt, __half* vb, int t) {
    // 256 rows x 64 halves (128B = 8 pieces)
    #pragma unroll
    for (int i = 0; i < 8; i++) {
        int idx = t + 256 * i;
        int c = idx >> 3, pc = idx & 7;
        cp16(vb + c * 72 + pc * 8, Vtg + (size_t)c * HWn + kt * 64 + pc * 8);
    }
}

__global__ void __launch_bounds__(256, 1) flash_kernel() {
    extern __shared__ __align__(16) __half smh[];
    __half* Qs  = smh + OFF_Q;
    __half* Kb[2] = { smh + OFF_K0, smh + OFF_K1 };
    __half* Vb[2] = { smh + OFF_VT0, smh + OFF_VT1 };
    __half* Ps  = smh + OFF_P;
    float* RF = (float*)(smh + HALFS_TOTAL);
    float* RM = RF;         // [2][64]
    float* RS = RF + 128;   // [2][64]

    int b = blockIdx.y;
    int qbase = blockIdx.x * 64;
    const __half* Qg  = g_q  + (size_t)b * HWn * Cc + (size_t)qbase * Cc;
    const __half* Kg  = g_k  + (size_t)b * HWn * Cc;
    const __half* Vtg = g_vt + (size_t)b * Cc * HWn;

    int t = threadIdx.x;
    int wid = t >> 5, lane = t & 31, g = lane >> 2, t4 = lane & 3;
    int mi = wid >> 1, ni = wid & 1;
    int wm = mi * 16;
    int qr0 = wm + g, qr1 = qr0 + 8;

    float oacc[16][4] = {};
    float M0 = -1e30f, M1 = -1e30f, L0 = 0.f, L1 = 0.f;

    // prologue: K0,V0 in flight (group for kt=0)
    copyK16(Kg, 0, Kb[0], t);
    copyV16(Vtg, 0, Vb[0], t);
    cpcommit();

    // Q tile: direct load (published by first syncthreads in the loop)
    #pragma unroll
    for (int i = 0; i < 8; i++) {
        int idx = t + 256 * i;
        int row = idx >> 5, pc = idx & 31;
        *(uint4*)&Qs[row * 264 + pc * 8] =
            *(const uint4*)(Qg + (size_t)row * Cc + pc * 8);
    }

    const uint32_t* Q2 = (const uint32_t*)Qs;
    const uint32_t* P2c = (const uint32_t*)Ps;
    uint32_t* P2 = (uint32_t*)Ps;

    for (int kt = 0; kt < 64; kt++) {
        int cur = kt & 1, nxt = cur ^ 1;
        if (kt < 63) {
            copyK16(Kg, kt + 1, Kb[nxt], t);
            copyV16(Vtg, kt + 1, Vb[nxt], t);
            cpcommit();
            cpwait<1>();
        } else {
            cpwait<0>();
        }
        __syncthreads();   // K/V(kt) + Q visible; prev-iter Ps free to overwrite

        // ---- S = Q Kᵀ : 16 k16 steps ----
        const uint32_t* K2 = (const uint32_t*)Kb[cur];
        float sacc[4][4] = {};
        #pragma unroll
        for (int ks = 0; ks < 16; ks++) {
            int ko = ks * 8;
            uint32_t a0 = Q2[qr0 * QP2 + ko + t4];
            uint32_t a1 = Q2[qr1 * QP2 + ko + t4];
            uint32_t a2 = Q2[qr0 * QP2 + ko + t4 + 4];
            uint32_t a3 = Q2[qr1 * QP2 + ko + t4 + 4];
            #pragma unroll
            for (int nt = 0; nt < 4; nt++) {
                int r = ni * 32 + nt * 8 + g;
                uint32_t b0 = K2[r * QP2 + ko + t4];
                uint32_t b1 = K2[r * QP2 + ko + t4 + 4];
                mma16(sacc[nt], a0, a1, a2, a3, b0, b1);
            }
        }

        // ---- online softmax (log2 domain; SCL = log2(e)/16) ----
        const float SCL = 0.090169311f;
        float mx0 = -1e30f, mx1 = -1e30f;
        #pragma unroll
        for (int nt = 0; nt < 4; nt++) {
            #pragma unroll
            for (int j = 0; j < 4; j++) sacc[nt][j] *= SCL;
            mx0 = fmaxf(mx0, fmaxf(sacc[nt][0], sacc[nt][1]));
            mx1 = fmaxf(mx1, fmaxf(sacc[nt][2], sacc[nt][3]));
        }
        mx0 = fmaxf(mx0, __shfl_xor_sync(0xffffffffu, mx0, 1));
        mx0 = fmaxf(mx0, __shfl_xor_sync(0xffffffffu, mx0, 2));
        mx1 = fmaxf(mx1, __shfl_xor_sync(0xffffffffu, mx1, 1));
        mx1 = fmaxf(mx1, __shfl_xor_sync(0xffffffffu, mx1, 2));
        if (t4 == 0) { RM[ni * 64 + qr0] = mx0; RM[ni * 64 + qr1] = mx1; }
        __syncthreads();
        float Mn0 = fmaxf(M0, fmaxf(RM[qr0], RM[64 + qr0]));
        float Mn1 = fmaxf(M1, fmaxf(RM[qr1], RM[64 + qr1]));
        float f0 = exp2f(M0 - Mn0), f1 = exp2f(M1 - Mn1);
        M0 = Mn0; M1 = Mn1;
        float s0 = 0.f, s1 = 0.f;
        #pragma unroll
        for (int nt = 0; nt < 4; nt++) {
            float p00 = exp2f(sacc[nt][0] - Mn0);
            float p01 = exp2f(sacc[nt][1] - Mn0);
            float p10 = exp2f(sacc[nt][2] - Mn1);
            float p11 = exp2f(sacc[nt][3] - Mn1);
            s0 += p00 + p01; s1 += p10 + p11;
            int ci = ni * 16 + nt * 4 + t4;       // half2 index along m
            __half2 u0 = __floats2half2_rn(p00, p01);
            __half2 u1 = __floats2half2_rn(p10, p11);
            P2[qr0 * PP2 + ci] = H2U(u0);
            P2[qr1 * PP2 + ci] = H2U(u1);
        }
        s0 += __shfl_xor_sync(0xffffffffu, s0, 1);
        s0 += __shfl_xor_sync(0xffffffffu, s0, 2);
        s1 += __shfl_xor_sync(0xffffffffu, s1, 1);
        s1 += __shfl_xor_sync(0xffffffffu, s1, 2);
        if (t4 == 0) { RS[ni * 64 + qr0] = s0; RS[ni * 64 + qr1] = s1; }
        __syncthreads();   // publishes Ps + RS
        L0 = L0 * f0 + RS[qr0] + RS[64 + qr0];
        L1 = L1 * f1 + RS[qr1] + RS[64 + qr1];
        #pragma unroll
        for (int nt2 = 0; nt2 < 16; nt2++) {
            oacc[nt2][0] *= f0; oacc[nt2][1] *= f0;
            oacc[nt2][2] *= f1; oacc[nt2][3] *= f1;
        }

        // ---- PV: oacc += P[64x64] @ V[64x256] (B from channel-major Vt) ----
        const uint32_t* V2 = (const uint32_t*)Vb[cur];
        #pragma unroll
        for (int km = 0; km < 4; km++) {
            int ko = km * 8;
            uint32_t a0 = P2c[qr0 * PP2 + ko + t4];
            uint32_t a1 = P2c[qr1 * PP2 + ko + t4];
            uint32_t a2 = P2c[qr0 * PP2 + ko + t4 + 4];
            uint32_t a3 = P2c[qr1 * PP2 + ko + t4 + 4];
            #pragma unroll
            for (int nt2 = 0; nt2 < 16; nt2++) {
                int c = ni * 128 + nt2 * 8 + g;
                uint32_t b0 = V2[c * VP2 + ko + t4];
                uint32_t b1 = V2[c * VP2 + ko + t4 + 4];
                mma16(oacc[nt2], a0, a1, a2, a3, b0, b1);
            }
        }
        __syncthreads();   // K/V(cur) + Ps consumed
    }

    float r0 = 1.0f / L0, r1 = 1.0f / L1;
    float* AO = g_ao + (size_t)b * HWn * Cc;
    int row0 = qbase + qr0;
    #pragma unroll
    for (int nt2 = 0; nt2 < 16; nt2++) {
        int c = ni * 128 + nt2 * 8 + t4 * 2;
        float2 v0 = { oacc[nt2][0] * r0, oacc[nt2][1] * r0 };
        float2 v1 = { oacc[nt2][2] * r1, oacc[nt2][3] * r1 };
        *(float2*)&AO[(size_t)row0 * Cc + c]       = v0;
        *(float2*)&AO[(size_t)(row0 + 8) * Cc + c] = v1;
    }
}

// ---------------- proj GEMM + residual -------------------------------------------
__global__ __launch_bounds__(256) void proj_kernel(const float* __restrict__ x,
                                                   const float* __restrict__ W,
                                                   const float* __restrict__ pb,
                                                   float* __restrict__ out) {
    __shared__ float As[128 * PA];
    __shared__ float Bs[128 * PA];
    int b = blockIdx.z;
    int om = blockIdx.y * 128;
    int pn = blockIdx.x * 128;
    const float* Ag = W + (size_t)om * Cc;
    const float* Bg = g_ao + (size_t)b * HWn * Cc + (size_t)pn * Cc;

    float acc[2][8][4] = {};
    gemm_nt(Ag, Bg, Cc, Cc, Cc, As, Bs, acc);

    int t = threadIdx.x, wid = t >> 5, lane = t & 31, g = lane >> 2, t4 = lane & 3;
    int wm = (wid >> 1) * 32, wn = (wid & 1) * 64;

    #pragma unroll
    for (int mt = 0; mt < 2; mt++) {
        int o0 = om + wm + mt * 16 + g;
        float b0 = pb[o0], b1 = pb[o0 + 8];
        #pragma unroll
        for (int nt = 0; nt < 8; nt++) {
            int p0 = pn + wn + nt * 8 + t4 * 2;
            size_t off0 = ((size_t)b * Cc + o0) * HWn + p0;
            size_t off1 = ((size_t)b * Cc + o0 + 8) * HWn + p0;
            float2 x0 = *(const float2*)&x[off0];
            float2 x1 = *(const float2*)&x[off1];
            float2 v0 = { acc[mt][nt][0] + b0 + x0.x, acc[mt][nt][1] + b0 + x0.y };
            float2 v1 = { acc[mt][nt][2] + b1 + x1.x, acc[mt][nt][3] + b1 + x1.y };
            *(float2*)&out[off0] = v0;
            *(float2*)&out[off1] = v1;
        }
    }
}

// ---------------- launch ---------------------------------------------------------
extern "C" void kernel_launch(void* const* d_in, const int* in_sizes, int n_in,
                              void* d_out, int out_size) {
    const float* x  = (const float*)d_in[0];
    const float* nw = (const float*)d_in[1];
    const float* nb = (const float*)d_in[2];
    const float* qw = (const float*)d_in[3];
    const float* qb = (const float*)d_in[4];
    const float* pw = (const float*)d_in[5];
    const float* pb = (const float*)d_in[6];
    float* out = (float*)d_out;

    cudaFuncSetAttribute(flash_kernel, cudaFuncAttributeMaxDynamicSharedMemorySize,
                         SMEM_BYTES);

    gn_kernel<<<Bn * 8, 512>>>(x, nw, nb);
    qkv_kernel<<<dim3(6, 32, 8), 256>>>(qw, qb);
    flash_kernel<<<dim3(64, 8), 256, SMEM_BYTES>>>();
    proj_kernel<<<dim3(32, 2, 8), 256>>>(x, pw, pb, out);
}

// round 7
// speedup vs baseline: 1.8593x; 1.2715x over previous
#include <cuda_runtime.h>
#include <cuda_fp16.h>
#include <cstdint>

#define Bn   8
#define Cc   256
#define HWn  4096
#define CPG  32
#define PA   20

// flash smem (half offsets); pitches: Q/K rows 264 halves, Vt rows 72 halves
#define QPH 264
#define VPH 72
#define OFF_Q  0
#define OFF_K0 (64 * QPH)            // 16896
#define OFF_K1 (OFF_K0 + 64 * QPH)   // 33792
#define OFF_V0 (OFF_K1 + 64 * QPH)   // 50688
#define OFF_V1 (OFF_V0 + 256 * VPH)  // 69120
#define HTOT   (OFF_V1 + 256 * VPH)  // 87552 halves
#define SMEM_BYTES (HTOT * 2)        // 175104 B

// ---------------- scratch -----------------------------------------------------
__device__ float  g_xn[(size_t)Bn * HWn * Cc];
__device__ __half g_q [(size_t)Bn * HWn * Cc];   // token-major [b][p][c]
__device__ __half g_k [(size_t)Bn * HWn * Cc];   // token-major [b][p][c]
__device__ __half g_vt[(size_t)Bn * Cc * HWn];   // channel-major [b][c][m]
__device__ float  g_ao[(size_t)Bn * HWn * Cc];

// ---------------- helpers ------------------------------------------------------
__device__ __forceinline__ float tf32r(float x) {
    uint32_t r;
    asm("cvt.rna.tf32.f32 %0, %1;" : "=r"(r) : "f"(x));
    return __uint_as_float(r);
}
__device__ __forceinline__ float4 tf32r4(float4 v) {
    float4 o; o.x = tf32r(v.x); o.y = tf32r(v.y); o.z = tf32r(v.z); o.w = tf32r(v.w);
    return o;
}
__device__ __forceinline__ void mma8(float c[4], uint32_t a0, uint32_t a1, uint32_t a2,
                                     uint32_t a3, uint32_t b0, uint32_t b1) {
    asm("mma.sync.aligned.m16n8k8.row.col.f32.tf32.tf32.f32 "
        "{%0,%1,%2,%3},{%4,%5,%6,%7},{%8,%9},{%0,%1,%2,%3};"
        : "+f"(c[0]), "+f"(c[1]), "+f"(c[2]), "+f"(c[3])
        : "r"(a0), "r"(a1), "r"(a2), "r"(a3), "r"(b0), "r"(b1));
}
__device__ __forceinline__ void mma16(float c[4], uint32_t a0, uint32_t a1, uint32_t a2,
                                      uint32_t a3, uint32_t b0, uint32_t b1) {
    asm("mma.sync.aligned.m16n8k16.row.col.f32.f16.f16.f32 "
        "{%0,%1,%2,%3},{%4,%5,%6,%7},{%8,%9},{%0,%1,%2,%3};"
        : "+f"(c[0]), "+f"(c[1]), "+f"(c[2]), "+f"(c[3])
        : "r"(a0), "r"(a1), "r"(a2), "r"(a3), "r"(b0), "r"(b1));
}
__device__ __forceinline__ void ldsm4(uint32_t& r0, uint32_t& r1, uint32_t& r2,
                                      uint32_t& r3, uint32_t a) {
    asm volatile("ldmatrix.sync.aligned.m8n8.x4.shared.b16 {%0,%1,%2,%3}, [%4];"
        : "=r"(r0), "=r"(r1), "=r"(r2), "=r"(r3) : "r"(a));
}
#define U(x) __float_as_uint(x)
#define H2U(x) (*(const uint32_t*)&(x))

__device__ __forceinline__ void cp16(void* dst, const void* src) {
    uint32_t d = (uint32_t)__cvta_generic_to_shared(dst);
    asm volatile("cp.async.cg.shared.global [%0], [%1], 16;\n" :: "r"(d), "l"(src));
}
__device__ __forceinline__ void cpcommit() { asm volatile("cp.async.commit_group;\n"); }
template<int N> __device__ __forceinline__ void cpwait() {
    asm volatile("cp.async.wait_group %0;\n" :: "n"(N));
}

// ---------------- GroupNorm ----------------------------------------------------
__global__ __launch_bounds__(512) void gn_kernel(const float* __restrict__ x,
                                                 const float* __restrict__ w,
                                                 const float* __restrict__ bv) {
    int bg = blockIdx.x;
    int b = bg >> 3, g = bg & 7;
    const float* xb = x + ((size_t)b * Cc + (size_t)g * CPG) * HWn;
    const int NEL = CPG * HWn;

    float s = 0.f, ss = 0.f;
    for (int i = threadIdx.x; i < NEL; i += blockDim.x) {
        float v = xb[i];
        s += v; ss += v * v;
    }
    __shared__ float rs[32], rss[32];
    #pragma unroll
    for (int o = 16; o; o >>= 1) {
        s  += __shfl_down_sync(0xffffffffu, s, o);
        ss += __shfl_down_sync(0xffffffffu, ss, o);
    }
    int lane = threadIdx.x & 31, wid = threadIdx.x >> 5;
    if (lane == 0) { rs[wid] = s; rss[wid] = ss; }
    __syncthreads();
    if (wid == 0) {
        s  = (lane < 16) ? rs[lane]  : 0.f;
        ss = (lane < 16) ? rss[lane] : 0.f;
        #pragma unroll
        for (int o = 16; o; o >>= 1) {
            s  += __shfl_down_sync(0xffffffffu, s, o);
            ss += __shfl_down_sync(0xffffffffu, ss, o);
        }
        if (lane == 0) { rs[0] = s; rss[0] = ss; }
    }
    __syncthreads();
    float mean = rs[0] / (float)NEL;
    float var  = rss[0] / (float)NEL - mean * mean;
    float rstd = rsqrtf(var + 1e-5f);

    float* out = g_xn + (size_t)b * HWn * Cc + (size_t)g * CPG;
    for (int i = threadIdx.x; i < NEL; i += blockDim.x) {
        int c = i & 31;
        int p = i >> 5;
        float v = xb[(size_t)c * HWn + p];
        out[(size_t)p * Cc + c] = (v - mean) * rstd * w[g * CPG + c] + bv[g * CPG + c];
    }
}

// ---------------- tf32 NT mainloop (qkv / proj) ----------------------------------
__device__ __forceinline__ void gemm_nt(const float* __restrict__ Ag,
                                        const float* __restrict__ Bg,
                                        int K, int lda, int ldb,
                                        float* As, float* Bs,
                                        float acc[2][8][4]) {
    int t = threadIdx.x;
    int r = t >> 1, cc = (t & 1) * 8;
    int wid = t >> 5, lane = t & 31, g = lane >> 2, t4 = lane & 3;
    int wm = (wid >> 1) * 32, wn = (wid & 1) * 64;

    #pragma unroll 1
    for (int kb = 0; kb < K; kb += 16) {
        float4 av0 = *(const float4*)(Ag + (size_t)r * lda + kb + cc);
        float4 av1 = *(const float4*)(Ag + (size_t)r * lda + kb + cc + 4);
        float4 bv0 = *(const float4*)(Bg + (size_t)r * ldb + kb + cc);
        float4 bv1 = *(const float4*)(Bg + (size_t)r * ldb + kb + cc + 4);
        __syncthreads();
        *(float4*)&As[r * PA + cc]     = tf32r4(av0);
        *(float4*)&As[r * PA + cc + 4] = tf32r4(av1);
        *(float4*)&Bs[r * PA + cc]     = tf32r4(bv0);
        *(float4*)&Bs[r * PA + cc + 4] = tf32r4(bv1);
        __syncthreads();
        #pragma unroll
        for (int ks = 0; ks < 16; ks += 8) {
            uint32_t af[2][4];
            #pragma unroll
            for (int mt = 0; mt < 2; mt++) {
                int row = (wm + mt * 16 + g) * PA + ks + t4;
                af[mt][0] = U(As[row]);
                af[mt][1] = U(As[row + 8 * PA]);
                af[mt][2] = U(As[row + 4]);
                af[mt][3] = U(As[row + 8 * PA + 4]);
            }
            uint32_t bf[8][2];
            #pragma unroll
            for (int nt = 0; nt < 8; nt++) {
                int row = (wn + nt * 8 + g) * PA + ks + t4;
                bf[nt][0] = U(Bs[row]);
                bf[nt][1] = U(Bs[row + 4]);
            }
            #pragma unroll
            for (int mt = 0; mt < 2; mt++)
                #pragma unroll
                for (int nt = 0; nt < 8; nt++)
                    mma8(acc[mt][nt], af[mt][0], af[mt][1], af[mt][2], af[mt][3],
                         bf[nt][0], bf[nt][1]);
        }
    }
}

// ---------------- QKV GEMM: q,k fp16 token-major; v fp16 channel-major ----------
__global__ __launch_bounds__(256) void qkv_kernel(const float* __restrict__ W,
                                                  const float* __restrict__ bias) {
    __shared__ float As[128 * PA];
    __shared__ float Bs[128 * PA];
    int b = blockIdx.z;
    int pm = blockIdx.y * 128;
    int on = blockIdx.x * 128;
    const float* Ag = g_xn + (size_t)b * HWn * Cc + (size_t)pm * Cc;
    const float* Bg = W + (size_t)on * Cc;

    float acc[2][8][4] = {};
    gemm_nt(Ag, Bg, Cc, Cc, Cc, As, Bs, acc);

    int t = threadIdx.x, wid = t >> 5, lane = t & 31, g = lane >> 2, t4 = lane & 3;
    int wm = (wid >> 1) * 32, wn = (wid & 1) * 64;

    if (on < 512) {
        __half* dst = ((on < 256) ? g_q : g_k) + (size_t)b * HWn * Cc;
        int obase = on & 255;
        #pragma unroll
        for (int nt = 0; nt < 8; nt++) {
            int ocol = wn + nt * 8 + t4 * 2;
            float2 bb = *(const float2*)&bias[on + ocol];
            #pragma unroll
            for (int mt = 0; mt < 2; mt++) {
                int p0 = pm + wm + mt * 16 + g;
                __half2 v0 = __floats2half2_rn(acc[mt][nt][0] + bb.x, acc[mt][nt][1] + bb.y);
                __half2 v1 = __floats2half2_rn(acc[mt][nt][2] + bb.x, acc[mt][nt][3] + bb.y);
                *(__half2*)&dst[(size_t)p0 * Cc + obase + ocol]       = v0;
                *(__half2*)&dst[(size_t)(p0 + 8) * Cc + obase + ocol] = v1;
            }
        }
    } else {
        __half* dst = g_vt + (size_t)b * Cc * HWn;
        #pragma unroll
        for (int nt = 0; nt < 8; nt++) {
            int ocol = wn + nt * 8 + t4 * 2;
            int c0 = (on - 512) + ocol;
            float2 bb = *(const float2*)&bias[on + ocol];
            #pragma unroll
            for (int mt = 0; mt < 2; mt++) {
                int p0 = pm + wm + mt * 16 + g;
                dst[(size_t)c0 * HWn + p0]           = __float2half(acc[mt][nt][0] + bb.x);
                dst[(size_t)(c0 + 1) * HWn + p0]     = __float2half(acc[mt][nt][1] + bb.y);
                dst[(size_t)c0 * HWn + p0 + 8]       = __float2half(acc[mt][nt][2] + bb.x);
                dst[(size_t)(c0 + 1) * HWn + p0 + 8] = __float2half(acc[mt][nt][3] + bb.y);
            }
        }
    }
}

// ---------------- flash attention: ldmatrix + split softmax ---------------------
__device__ __forceinline__ void copyK16(const __half* Kg, int kt, __half* kb, int t) {
    #pragma unroll
    for (int i = 0; i < 8; i++) {
        int idx = t + 256 * i;
        int row = idx >> 5, pc = idx & 31;
        cp16(kb + row * QPH + pc * 8, Kg + (size_t)(kt * 64 + row) * Cc + pc * 8);
    }
}
__device__ __forceinline__ void copyV16(const __half* Vtg, int kt, __half* vb, int t) {
    #pragma unroll
    for (int i = 0; i < 8; i++) {
        int idx = t + 256 * i;
        int c = idx >> 3, pc = idx & 7;
        cp16(vb + c * VPH + pc * 8, Vtg + (size_t)c * HWn + kt * 64 + pc * 8);
    }
}

__global__ void __launch_bounds__(256, 1) flash_kernel() {
    extern __shared__ __align__(16) __half smh[];
    int b = blockIdx.y;
    int qbase = blockIdx.x * 64;
    const __half* Qg  = g_q  + (size_t)b * HWn * Cc + (size_t)qbase * Cc;
    const __half* Kg  = g_k  + (size_t)b * HWn * Cc;
    const __half* Vtg = g_vt + (size_t)b * Cc * HWn;

    int t = threadIdx.x;
    int wid = t >> 5, lane = t & 31, g = lane >> 2, t4 = lane & 3;
    int mi = wid >> 1, ni = wid & 1;
    int wm = mi * 16;

    uint32_t sb = (uint32_t)__cvta_generic_to_shared(smh);
    // ldmatrix per-lane base addresses (bytes)
    uint32_t aQ = sb + (uint32_t)(OFF_Q + (wm + (lane & 15)) * QPH + (lane >> 4) * 8) * 2;
    uint32_t rowKV = (uint32_t)(((lane >> 4) << 3) + (lane & 7));   // 0..15
    uint32_t colHi = (uint32_t)(((lane >> 3) & 1) << 3);            // 0 or 8 halves
    uint32_t aK0 = sb + (uint32_t)(OFF_K0 + (ni * 32 + rowKV) * QPH + colHi) * 2;
    uint32_t aK1 = aK0 + (uint32_t)(OFF_K1 - OFF_K0) * 2;
    uint32_t aV0 = sb + (uint32_t)(OFF_V0 + rowKV * VPH + ni * 32 + colHi) * 2;
    uint32_t aV1 = aV0 + (uint32_t)(OFF_V1 - OFF_V0) * 2;

    float oacc[32][4] = {};
    float M0 = -1e30f, M1 = -1e30f, L0 = 0.f, L1 = 0.f;

    // prologue: K0,V0 in flight
    copyK16(Kg, 0, smh + OFF_K0, t);
    copyV16(Vtg, 0, smh + OFF_V0, t);
    cpcommit();

    // Q tile into smem (plain stores; published by first barrier)
    #pragma unroll
    for (int i = 0; i < 8; i++) {
        int idx = t + 256 * i;
        int row = idx >> 5, pc = idx & 31;
        *(uint4*)&smh[OFF_Q + row * QPH + pc * 8] =
            *(const uint4*)(Qg + (size_t)row * Cc + pc * 8);
    }

    for (int kt = 0; kt < 64; kt++) {
        int cur = kt & 1;
        if (kt < 63) {
            copyK16(Kg, kt + 1, smh + (cur ? OFF_K0 : OFF_K1), t);
            copyV16(Vtg, kt + 1, smh + (cur ? OFF_V0 : OFF_V1), t);
            cpcommit();
            cpwait<1>();
        } else {
            cpwait<0>();
        }
        __syncthreads();   // buf[cur] visible to all

        // ---- S[16q x 32m] = Q Kᵀ (warp-local m-half) ----
        uint32_t kb = cur ? aK1 : aK0;
        float sacc[4][4] = {};
        #pragma unroll
        for (int ks = 0; ks < 16; ks++) {
            uint32_t qa0, qa1, qa2, qa3;
            ldsm4(qa0, qa1, qa2, qa3, aQ + ks * 32);
            #pragma unroll
            for (int ntp = 0; ntp < 2; ntp++) {
                uint32_t b0, b1, b2, b3;
                ldsm4(b0, b1, b2, b3, kb + ntp * (16 * QPH * 2) + ks * 32);
                mma16(sacc[ntp * 2],     qa0, qa1, qa2, qa3, b0, b1);
                mma16(sacc[ntp * 2 + 1], qa0, qa1, qa2, qa3, b2, b3);
            }
        }

        // ---- warp-local online softmax (log2 domain; SCL = log2(e)/16) ----
        const float SCL = 0.09016844f;
        float mx0 = -1e30f, mx1 = -1e30f;
        #pragma unroll
        for (int nt = 0; nt < 4; nt++) {
            #pragma unroll
            for (int j = 0; j < 4; j++) sacc[nt][j] *= SCL;
            mx0 = fmaxf(mx0, fmaxf(sacc[nt][0], sacc[nt][1]));
            mx1 = fmaxf(mx1, fmaxf(sacc[nt][2], sacc[nt][3]));
        }
        mx0 = fmaxf(mx0, __shfl_xor_sync(0xffffffffu, mx0, 1));
        mx0 = fmaxf(mx0, __shfl_xor_sync(0xffffffffu, mx0, 2));
        mx1 = fmaxf(mx1, __shfl_xor_sync(0xffffffffu, mx1, 1));
        mx1 = fmaxf(mx1, __shfl_xor_sync(0xffffffffu, mx1, 2));
        float Mn0 = fmaxf(M0, mx0), Mn1 = fmaxf(M1, mx1);
        float f0 = exp2f(M0 - Mn0), f1 = exp2f(M1 - Mn1);
        M0 = Mn0; M1 = Mn1;

        float p[4][4];
        float s0 = 0.f, s1 = 0.f;
        #pragma unroll
        for (int nt = 0; nt < 4; nt++) {
            p[nt][0] = exp2f(sacc[nt][0] - Mn0);
            p[nt][1] = exp2f(sacc[nt][1] - Mn0);
            p[nt][2] = exp2f(sacc[nt][2] - Mn1);
            p[nt][3] = exp2f(sacc[nt][3] - Mn1);
            s0 += p[nt][0] + p[nt][1];
            s1 += p[nt][2] + p[nt][3];
        }
        s0 += __shfl_xor_sync(0xffffffffu, s0, 1);
        s0 += __shfl_xor_sync(0xffffffffu, s0, 2);
        s1 += __shfl_xor_sync(0xffffffffu, s1, 1);
        s1 += __shfl_xor_sync(0xffffffffu, s1, 2);
        L0 = L0 * f0 + s0;
        L1 = L1 * f1 + s1;

        // P fragments stay in registers (A-frag layout == sacc layout)
        uint32_t pa[2][4];
        #pragma unroll
        for (int km = 0; km < 2; km++) {
            __half2 h0 = __floats2half2_rn(p[2*km][0],   p[2*km][1]);
            __half2 h1 = __floats2half2_rn(p[2*km][2],   p[2*km][3]);
            __half2 h2 = __floats2half2_rn(p[2*km+1][0], p[2*km+1][1]);
            __half2 h3 = __floats2half2_rn(p[2*km+1][2], p[2*km+1][3]);
            pa[km][0] = H2U(h0); pa[km][1] = H2U(h1);
            pa[km][2] = H2U(h2); pa[km][3] = H2U(h3);
        }

        #pragma unroll
        for (int ct = 0; ct < 32; ct++) {
            oacc[ct][0] *= f0; oacc[ct][1] *= f0;
            oacc[ct][2] *= f1; oacc[ct][3] *= f1;
        }

        // ---- PV: O[16q x 256c] += P[16 x 32] @ V[32 x 256] ----
        uint32_t vb = cur ? aV1 : aV0;
        #pragma unroll
        for (int km = 0; km < 2; km++) {
            #pragma unroll
            for (int ct = 0; ct < 16; ct++) {
                uint32_t v0, v1, v2, v3;
                ldsm4(v0, v1, v2, v3, vb + ct * (16 * VPH * 2) + km * 32);
                mma16(oacc[ct * 2],     pa[km][0], pa[km][1], pa[km][2], pa[km][3], v0, v1);
                mma16(oacc[ct * 2 + 1], pa[km][0], pa[km][1], pa[km][2], pa[km][3], v2, v3);
            }
        }
        __syncthreads();   // all reads of buf[cur] done before kt+1 overwrites
    }

    // ---- merge the two ni halves (smem reused; after final barrier) -----------
    float* OB = (float*)smh;            // 64 x 260 fp32
    float* MB = OB + 64 * 260;
    float* LB = MB + 64;
    int r0 = wm + g, r1 = r0 + 8;

    if (ni == 1) {
        if (t4 == 0) { MB[r0] = M0; MB[r1] = M1; LB[r0] = L0; LB[r1] = L1; }
        #pragma unroll
        for (int ct = 0; ct < 32; ct++) {
            int c = ct * 8 + t4 * 2;
            *(float2*)&OB[r0 * 260 + c] = make_float2(oacc[ct][0], oacc[ct][1]);
            *(float2*)&OB[r1 * 260 + c] = make_float2(oacc[ct][2], oacc[ct][3]);
        }
    }
    __syncthreads();
    if (ni == 0) {
        float Mo0 = MB[r0], Mo1 = MB[r1];
        float Lo0 = LB[r0], Lo1 = LB[r1];
        float Mf0 = fmaxf(M0, Mo0), Mf1 = fmaxf(M1, Mo1);
        float w00 = exp2f(M0 - Mf0), w01 = exp2f(Mo0 - Mf0);
        float w10 = exp2f(M1 - Mf1), w11 = exp2f(Mo1 - Mf1);
        float inv0 = 1.0f / (w00 * L0 + w01 * Lo0);
        float inv1 = 1.0f / (w10 * L1 + w11 * Lo1);
        float* AO = g_ao + (size_t)b * HWn * Cc;
        #pragma unroll
        for (int ct = 0; ct < 32; ct++) {
            int c = ct * 8 + t4 * 2;
            float2 o1a = *(const float2*)&OB[r0 * 260 + c];
            float2 o1b = *(const float2*)&OB[r1 * 260 + c];
            float2 va = { (w00 * oacc[ct][0] + w01 * o1a.x) * inv0,
                          (w00 * oacc[ct][1] + w01 * o1a.y) * inv0 };
            float2 vbv = { (w10 * oacc[ct][2] + w11 * o1b.x) * inv1,
                           (w10 * oacc[ct][3] + w11 * o1b.y) * inv1 };
            *(float2*)&AO[(size_t)(qbase + r0) * Cc + c] = va;
            *(float2*)&AO[(size_t)(qbase + r1) * Cc + c] = vbv;
        }
    }
}

// ---------------- proj GEMM + residual -------------------------------------------
__global__ __launch_bounds__(256) void proj_kernel(const float* __restrict__ x,
                                                   const float* __restrict__ W,
                                                   const float* __restrict__ pb,
                                                   float* __restrict__ out) {
    __shared__ float As[128 * PA];
    __shared__ float Bs[128 * PA];
    int b = blockIdx.z;
    int om = blockIdx.y * 128;
    int pn = blockIdx.x * 128;
    const float* Ag = W + (size_t)om * Cc;
    const float* Bg = g_ao + (size_t)b * HWn * Cc + (size_t)pn * Cc;

    float acc[2][8][4] = {};
    gemm_nt(Ag, Bg, Cc, Cc, Cc, As, Bs, acc);

    int t = threadIdx.x, wid = t >> 5, lane = t & 31, g = lane >> 2, t4 = lane & 3;
    int wm = (wid >> 1) * 32, wn = (wid & 1) * 64;

    #pragma unroll
    for (int mt = 0; mt < 2; mt++) {
        int o0 = om + wm + mt * 16 + g;
        float b0 = pb[o0], b1 = pb[o0 + 8];
        #pragma unroll
        for (int nt = 0; nt < 8; nt++) {
            int p0 = pn + wn + nt * 8 + t4 * 2;
            size_t off0 = ((size_t)b * Cc + o0) * HWn + p0;
            size_t off1 = ((size_t)b * Cc + o0 + 8) * HWn + p0;
            float2 x0 = *(const float2*)&x[off0];
            float2 x1 = *(const float2*)&x[off1];
            float2 v0 = { acc[mt][nt][0] + b0 + x0.x, acc[mt][nt][1] + b0 + x0.y };
            float2 v1 = { acc[mt][nt][2] + b1 + x1.x, acc[mt][nt][3] + b1 + x1.y };
            *(float2*)&out[off0] = v0;
            *(float2*)&out[off1] = v1;
        }
    }
}

// ---------------- launch ---------------------------------------------------------
extern "C" void kernel_launch(void* const* d_in, const int* in_sizes, int n_in,
                              void* d_out, int out_size) {
    const float* x  = (const float*)d_in[0];
    const float* nw = (const float*)d_in[1];
    const float* nb = (const float*)d_in[2];
    const float* qw = (const float*)d_in[3];
    const float* qb = (const float*)d_in[4];
    const float* pw = (const float*)d_in[5];
    const float* pb = (const float*)d_in[6];
    float* out = (float*)d_out;

    cudaFuncSetAttribute(flash_kernel, cudaFuncAttributeMaxDynamicSharedMemorySize,
                         SMEM_BYTES);

    gn_kernel<<<Bn * 8, 512>>>(x, nw, nb);
    qkv_kernel<<<dim3(6, 32, 8), 256>>>(qw, qb);
    flash_kernel<<<dim3(64, 8), 256, SMEM_BYTES>>>();
    proj_kernel<<<dim3(32, 2, 8), 256>>>(x, pw, pb, out);
}

// round 8
// speedup vs baseline: 2.0286x; 1.0911x over previous
#include <cuda_runtime.h>
#include <cuda_fp16.h>
#include <cstdint>

#define Bn   8
#define Cc   256
#define HWn  4096
#define CPG  32

// flash smem (half offsets); pitches: Q/K rows 264 halves, Vt rows 72 halves
#define QPH 264
#define VPH 72
#define OFF_Q  0
#define OFF_K0 (64 * QPH)
#define OFF_K1 (OFF_K0 + 64 * QPH)
#define OFF_V0 (OFF_K1 + 64 * QPH)
#define OFF_V1 (OFF_V0 + 256 * VPH)
#define HTOT   (OFF_V1 + 256 * VPH)
#define SMEM_BYTES (HTOT * 2)          // 175104 B

// fp16 GEMM tiles (qkv/proj): A,B each 128 x 264 halves
#define GP  264
#define GEMM_SMEM (2 * 128 * GP * 2)   // 135168 B

// ---------------- scratch -----------------------------------------------------
__device__ __half g_xnh[(size_t)Bn * HWn * Cc];  // GN out fp16, token-major
__device__ __half g_qwh[768 * 256];              // qkv weight fp16
__device__ __half g_pwh[256 * 256];              // proj weight fp16
__device__ __half g_q [(size_t)Bn * HWn * Cc];   // [b][p][c]
__device__ __half g_k [(size_t)Bn * HWn * Cc];   // [b][p][c]
__device__ __half g_vt[(size_t)Bn * Cc * HWn];   // [b][c][m]
__device__ __half g_aoh[(size_t)Bn * HWn * Cc];  // attn out fp16, token-major

// ---------------- helpers ------------------------------------------------------
__device__ __forceinline__ void mma16(float c[4], uint32_t a0, uint32_t a1, uint32_t a2,
                                      uint32_t a3, uint32_t b0, uint32_t b1) {
    asm("mma.sync.aligned.m16n8k16.row.col.f32.f16.f16.f32 "
        "{%0,%1,%2,%3},{%4,%5,%6,%7},{%8,%9},{%0,%1,%2,%3};"
        : "+f"(c[0]), "+f"(c[1]), "+f"(c[2]), "+f"(c[3])
        : "r"(a0), "r"(a1), "r"(a2), "r"(a3), "r"(b0), "r"(b1));
}
__device__ __forceinline__ void ldsm4(uint32_t& r0, uint32_t& r1, uint32_t& r2,
                                      uint32_t& r3, uint32_t a) {
    asm volatile("ldmatrix.sync.aligned.m8n8.x4.shared.b16 {%0,%1,%2,%3}, [%4];"
        : "=r"(r0), "=r"(r1), "=r"(r2), "=r"(r3) : "r"(a));
}
#define H2U(x) (*(const uint32_t*)&(x))

__device__ __forceinline__ void cp16(void* dst, const void* src) {
    uint32_t d = (uint32_t)__cvta_generic_to_shared(dst);
    asm volatile("cp.async.cg.shared.global [%0], [%1], 16;\n" :: "r"(d), "l"(src));
}
__device__ __forceinline__ void cpcommit() { asm volatile("cp.async.commit_group;\n"); }
template<int N> __device__ __forceinline__ void cpwait() {
    asm volatile("cp.async.wait_group %0;\n" :: "n"(N));
}

// ---------------- weight fp32 -> fp16 conversion --------------------------------
__global__ __launch_bounds__(256) void wconv_kernel(const float* __restrict__ qw,
                                                    const float* __restrict__ pw) {
    int i = blockIdx.x * 256 + threadIdx.x;
    if (i < 768 * 256) g_qwh[i] = __float2half(qw[i]);
    if (i < 256 * 256) g_pwh[i] = __float2half(pw[i]);
}

// ---------------- GroupNorm (fp16 out, token-major) -----------------------------
__global__ __launch_bounds__(512) void gn_kernel(const float* __restrict__ x,
                                                 const float* __restrict__ w,
                                                 const float* __restrict__ bv) {
    int bg = blockIdx.x;
    int b = bg >> 3, g = bg & 7;
    const float* xb = x + ((size_t)b * Cc + (size_t)g * CPG) * HWn;
    const int NEL = CPG * HWn;

    float s = 0.f, ss = 0.f;
    for (int i = threadIdx.x; i < NEL; i += blockDim.x) {
        float v = xb[i];
        s += v; ss += v * v;
    }
    __shared__ float rs[32], rss[32];
    #pragma unroll
    for (int o = 16; o; o >>= 1) {
        s  += __shfl_down_sync(0xffffffffu, s, o);
        ss += __shfl_down_sync(0xffffffffu, ss, o);
    }
    int lane = threadIdx.x & 31, wid = threadIdx.x >> 5;
    if (lane == 0) { rs[wid] = s; rss[wid] = ss; }
    __syncthreads();
    if (wid == 0) {
        s  = (lane < 16) ? rs[lane]  : 0.f;
        ss = (lane < 16) ? rss[lane] : 0.f;
        #pragma unroll
        for (int o = 16; o; o >>= 1) {
            s  += __shfl_down_sync(0xffffffffu, s, o);
            ss += __shfl_down_sync(0xffffffffu, ss, o);
        }
        if (lane == 0) { rs[0] = s; rss[0] = ss; }
    }
    __syncthreads();
    float mean = rs[0] / (float)NEL;
    float var  = rss[0] / (float)NEL - mean * mean;
    float rstd = rsqrtf(var + 1e-5f);

    __half* out = g_xnh + (size_t)b * HWn * Cc + (size_t)g * CPG;
    for (int i = threadIdx.x; i < NEL; i += blockDim.x) {
        int c = i & 31;
        int p = i >> 5;
        float v = xb[(size_t)c * HWn + p];
        out[(size_t)p * Cc + c] =
            __float2half((v - mean) * rstd * w[g * CPG + c] + bv[g * CPG + c]);
    }
}

// ---------------- fp16 NT GEMM core: acc[2][8][4] = A[128,256] B[128,256]^T -----
// A, B: global fp16, row stride 256 halves. smem dynamic: A at 0, B at 128*GP.
__device__ __forceinline__ void gemm16(const __half* __restrict__ Ag,
                                       const __half* __restrict__ Bg,
                                       __half* gsm, float acc[2][8][4]) {
    int t = threadIdx.x;
    // load both tiles (K=256 fully resident)
    #pragma unroll
    for (int i = 0; i < 16; i++) {
        int idx = t + 256 * i;
        int row = idx >> 5, pc = idx & 31;
        cp16(gsm + row * GP + pc * 8, Ag + (size_t)row * 256 + pc * 8);
        cp16(gsm + 128 * GP + row * GP + pc * 8, Bg + (size_t)row * 256 + pc * 8);
    }
    cpcommit();
    cpwait<0>();
    __syncthreads();

    int wid = t >> 5, lane = t & 31;
    int wm = (wid >> 1) * 32, wn = (wid & 1) * 64;
    uint32_t sb = (uint32_t)__cvta_generic_to_shared(gsm);
    uint32_t aA = sb + (uint32_t)((wm + (lane & 15)) * GP + (lane >> 4) * 8) * 2;
    uint32_t rowKV = (uint32_t)(((lane >> 4) << 3) + (lane & 7));
    uint32_t colHi = (uint32_t)(((lane >> 3) & 1) << 3);
    uint32_t aB = sb + (uint32_t)(128 * GP + (wn + rowKV) * GP + colHi) * 2;

    #pragma unroll
    for (int ks = 0; ks < 16; ks++) {
        uint32_t a[2][4];
        ldsm4(a[0][0], a[0][1], a[0][2], a[0][3], aA + ks * 32);
        ldsm4(a[1][0], a[1][1], a[1][2], a[1][3], aA + 16 * GP * 2 + ks * 32);
        #pragma unroll
        for (int ng = 0; ng < 4; ng++) {
            uint32_t b0, b1, b2, b3;
            ldsm4(b0, b1, b2, b3, aB + ng * (16 * GP * 2) + ks * 32);
            #pragma unroll
            for (int mt = 0; mt < 2; mt++) {
                mma16(acc[mt][ng * 2],     a[mt][0], a[mt][1], a[mt][2], a[mt][3], b0, b1);
                mma16(acc[mt][ng * 2 + 1], a[mt][0], a[mt][1], a[mt][2], a[mt][3], b2, b3);
            }
        }
    }
}

// ---------------- QKV GEMM (fp16): q,k token-major; v channel-major -------------
__global__ __launch_bounds__(256) void qkv_kernel(const float* __restrict__ bias) {
    extern __shared__ __align__(16) __half gsm[];
    int b = blockIdx.z;
    int pm = blockIdx.y * 128;
    int on = blockIdx.x * 128;
    const __half* Ag = g_xnh + (size_t)b * HWn * Cc + (size_t)pm * Cc;
    const __half* Bg = g_qwh + (size_t)on * Cc;

    float acc[2][8][4] = {};
    gemm16(Ag, Bg, gsm, acc);

    int t = threadIdx.x, wid = t >> 5, lane = t & 31, g = lane >> 2, t4 = lane & 3;
    int wm = (wid >> 1) * 32, wn = (wid & 1) * 64;

    if (on < 512) {
        __half* dst = ((on < 256) ? g_q : g_k) + (size_t)b * HWn * Cc;
        int obase = on & 255;
        #pragma unroll
        for (int nt = 0; nt < 8; nt++) {
            int ocol = wn + nt * 8 + t4 * 2;
            float2 bb = *(const float2*)&bias[on + ocol];
            #pragma unroll
            for (int mt = 0; mt < 2; mt++) {
                int p0 = pm + wm + mt * 16 + g;
                __half2 v0 = __floats2half2_rn(acc[mt][nt][0] + bb.x, acc[mt][nt][1] + bb.y);
                __half2 v1 = __floats2half2_rn(acc[mt][nt][2] + bb.x, acc[mt][nt][3] + bb.y);
                *(__half2*)&dst[(size_t)p0 * Cc + obase + ocol]       = v0;
                *(__half2*)&dst[(size_t)(p0 + 8) * Cc + obase + ocol] = v1;
            }
        }
    } else {
        __half* dst = g_vt + (size_t)b * Cc * HWn;
        #pragma unroll
        for (int nt = 0; nt < 8; nt++) {
            int ocol = wn + nt * 8 + t4 * 2;
            int c0 = (on - 512) + ocol;
            float2 bb = *(const float2*)&bias[on + ocol];
            #pragma unroll
            for (int mt = 0; mt < 2; mt++) {
                int p0 = pm + wm + mt * 16 + g;
                dst[(size_t)c0 * HWn + p0]           = __float2half(acc[mt][nt][0] + bb.x);
                dst[(size_t)(c0 + 1) * HWn + p0]     = __float2half(acc[mt][nt][1] + bb.y);
                dst[(size_t)c0 * HWn + p0 + 8]       = __float2half(acc[mt][nt][2] + bb.x);
                dst[(size_t)(c0 + 1) * HWn + p0 + 8] = __float2half(acc[mt][nt][3] + bb.y);
            }
        }
    }
}

// ---------------- flash attention: Q-in-registers + split softmax ---------------
__device__ __forceinline__ void copyK16(const __half* Kg, int kt, __half* kb, int t) {
    #pragma unroll
    for (int i = 0; i < 8; i++) {
        int idx = t + 256 * i;
        int row = idx >> 5, pc = idx & 31;
        cp16(kb + row * QPH + pc * 8, Kg + (size_t)(kt * 64 + row) * Cc + pc * 8);
    }
}
__device__ __forceinline__ void copyV16(const __half* Vtg, int kt, __half* vb, int t) {
    #pragma unroll
    for (int i = 0; i < 8; i++) {
        int idx = t + 256 * i;
        int c = idx >> 3, pc = idx & 7;
        cp16(vb + c * VPH + pc * 8, Vtg + (size_t)c * HWn + kt * 64 + pc * 8);
    }
}

__global__ void __launch_bounds__(256, 1) flash_kernel() {
    extern __shared__ __align__(16) __half smh[];
    int b = blockIdx.y;
    int qbase = blockIdx.x * 64;
    const __half* Qg  = g_q  + (size_t)b * HWn * Cc + (size_t)qbase * Cc;
    const __half* Kg  = g_k  + (size_t)b * HWn * Cc;
    const __half* Vtg = g_vt + (size_t)b * Cc * HWn;

    int t = threadIdx.x;
    int wid = t >> 5, lane = t & 31, g = lane >> 2, t4 = lane & 3;
    int mi = wid >> 1, ni = wid & 1;
    int wm = mi * 16;

    uint32_t sb = (uint32_t)__cvta_generic_to_shared(smh);
    uint32_t aQ = sb + (uint32_t)(OFF_Q + (wm + (lane & 15)) * QPH + (lane >> 4) * 8) * 2;
    uint32_t rowKV = (uint32_t)(((lane >> 4) << 3) + (lane & 7));
    uint32_t colHi = (uint32_t)(((lane >> 3) & 1) << 3);
    uint32_t aK0 = sb + (uint32_t)(OFF_K0 + (ni * 32 + rowKV) * QPH + colHi) * 2;
    uint32_t aK1 = aK0 + (uint32_t)(OFF_K1 - OFF_K0) * 2;
    uint32_t aV0 = sb + (uint32_t)(OFF_V0 + rowKV * VPH + ni * 32 + colHi) * 2;
    uint32_t aV1 = aV0 + (uint32_t)(OFF_V1 - OFF_V0) * 2;

    float oacc[32][4] = {};
    float M0 = -1e30f, M1 = -1e30f, L0 = 0.f, L1 = 0.f;

    // prologue: K0,V0 in flight
    copyK16(Kg, 0, smh + OFF_K0, t);
    copyV16(Vtg, 0, smh + OFF_V0, t);
    cpcommit();

    // Q tile -> smem -> registers (once)
    #pragma unroll
    for (int i = 0; i < 8; i++) {
        int idx = t + 256 * i;
        int row = idx >> 5, pc = idx & 31;
        *(uint4*)&smh[OFF_Q + row * QPH + pc * 8] =
            *(const uint4*)(Qg + (size_t)row * Cc + pc * 8);
    }
    __syncthreads();
    uint32_t qa[16][4];
    #pragma unroll
    for (int ks = 0; ks < 16; ks++)
        ldsm4(qa[ks][0], qa[ks][1], qa[ks][2], qa[ks][3], aQ + ks * 32);

    for (int kt = 0; kt < 64; kt++) {
        int cur = kt & 1;
        if (kt < 63) {
            copyK16(Kg, kt + 1, smh + (cur ? OFF_K0 : OFF_K1), t);
            copyV16(Vtg, kt + 1, smh + (cur ? OFF_V0 : OFF_V1), t);
            cpcommit();
            cpwait<1>();
        } else {
            cpwait<0>();
        }
        __syncthreads();

        // ---- S[16q x 32m] ----
        uint32_t kb = cur ? aK1 : aK0;
        float sacc[4][4] = {};
        #pragma unroll
        for (int ks = 0; ks < 16; ks++) {
            #pragma unroll
            for (int ntp = 0; ntp < 2; ntp++) {
                uint32_t b0, b1, b2, b3;
                ldsm4(b0, b1, b2, b3, kb + ntp * (16 * QPH * 2) + ks * 32);
                mma16(sacc[ntp * 2],     qa[ks][0], qa[ks][1], qa[ks][2], qa[ks][3], b0, b1);
                mma16(sacc[ntp * 2 + 1], qa[ks][0], qa[ks][1], qa[ks][2], qa[ks][3], b2, b3);
            }
        }

        // ---- warp-local online softmax (log2 domain) ----
        const float SCL = 0.09016844f;
        float mx0 = -1e30f, mx1 = -1e30f;
        #pragma unroll
        for (int nt = 0; nt < 4; nt++) {
            #pragma unroll
            for (int j = 0; j < 4; j++) sacc[nt][j] *= SCL;
            mx0 = fmaxf(mx0, fmaxf(sacc[nt][0], sacc[nt][1]));
            mx1 = fmaxf(mx1, fmaxf(sacc[nt][2], sacc[nt][3]));
        }
        mx0 = fmaxf(mx0, __shfl_xor_sync(0xffffffffu, mx0, 1));
        mx0 = fmaxf(mx0, __shfl_xor_sync(0xffffffffu, mx0, 2));
        mx1 = fmaxf(mx1, __shfl_xor_sync(0xffffffffu, mx1, 1));
        mx1 = fmaxf(mx1, __shfl_xor_sync(0xffffffffu, mx1, 2));
        float Mn0 = fmaxf(M0, mx0), Mn1 = fmaxf(M1, mx1);
        float f0 = exp2f(M0 - Mn0), f1 = exp2f(M1 - Mn1);
        M0 = Mn0; M1 = Mn1;

        float p[4][4];
        float s0 = 0.f, s1 = 0.f;
        #pragma unroll
        for (int nt = 0; nt < 4; nt++) {
            p[nt][0] = exp2f(sacc[nt][0] - Mn0);
            p[nt][1] = exp2f(sacc[nt][1] - Mn0);
            p[nt][2] = exp2f(sacc[nt][2] - Mn1);
            p[nt][3] = exp2f(sacc[nt][3] - Mn1);
            s0 += p[nt][0] + p[nt][1];
            s1 += p[nt][2] + p[nt][3];
        }
        s0 += __shfl_xor_sync(0xffffffffu, s0, 1);
        s0 += __shfl_xor_sync(0xffffffffu, s0, 2);
        s1 += __shfl_xor_sync(0xffffffffu, s1, 1);
        s1 += __shfl_xor_sync(0xffffffffu, s1, 2);
        L0 = L0 * f0 + s0;
        L1 = L1 * f1 + s1;

        uint32_t pa[2][4];
        #pragma unroll
        for (int km = 0; km < 2; km++) {
            __half2 h0 = __floats2half2_rn(p[2*km][0],   p[2*km][1]);
            __half2 h1 = __floats2half2_rn(p[2*km][2],   p[2*km][3]);
            __half2 h2 = __floats2half2_rn(p[2*km+1][0], p[2*km+1][1]);
            __half2 h3 = __floats2half2_rn(p[2*km+1][2], p[2*km+1][3]);
            pa[km][0] = H2U(h0); pa[km][1] = H2U(h1);
            pa[km][2] = H2U(h2); pa[km][3] = H2U(h3);
        }

        #pragma unroll
        for (int ct = 0; ct < 32; ct++) {
            oacc[ct][0] *= f0; oacc[ct][1] *= f0;
            oacc[ct][2] *= f1; oacc[ct][3] *= f1;
        }

        // ---- PV ----
        uint32_t vb = cur ? aV1 : aV0;
        #pragma unroll
        for (int km = 0; km < 2; km++) {
            #pragma unroll
            for (int ct = 0; ct < 16; ct++) {
                uint32_t v0, v1, v2, v3;
                ldsm4(v0, v1, v2, v3, vb + ct * (16 * VPH * 2) + km * 32);
                mma16(oacc[ct * 2],     pa[km][0], pa[km][1], pa[km][2], pa[km][3], v0, v1);
                mma16(oacc[ct * 2 + 1], pa[km][0], pa[km][1], pa[km][2], pa[km][3], v2, v3);
            }
        }
        __syncthreads();
    }

    // ---- merge the two ni halves ----
    float* OB = (float*)smh;            // 64 x 260 fp32
    float* MB = OB + 64 * 260;
    float* LB = MB + 64;
    int r0 = wm + g, r1 = r0 + 8;

    if (ni == 1) {
        if (t4 == 0) { MB[r0] = M0; MB[r1] = M1; LB[r0] = L0; LB[r1] = L1; }
        #pragma unroll
        for (int ct = 0; ct < 32; ct++) {
            int c = ct * 8 + t4 * 2;
            *(float2*)&OB[r0 * 260 + c] = make_float2(oacc[ct][0], oacc[ct][1]);
            *(float2*)&OB[r1 * 260 + c] = make_float2(oacc[ct][2], oacc[ct][3]);
        }
    }
    __syncthreads();
    if (ni == 0) {
        float Mo0 = MB[r0], Mo1 = MB[r1];
        float Lo0 = LB[r0], Lo1 = LB[r1];
        float Mf0 = fmaxf(M0, Mo0), Mf1 = fmaxf(M1, Mo1);
        float w00 = exp2f(M0 - Mf0), w01 = exp2f(Mo0 - Mf0);
        float w10 = exp2f(M1 - Mf1), w11 = exp2f(Mo1 - Mf1);
        float inv0 = 1.0f / (w00 * L0 + w01 * Lo0);
        float inv1 = 1.0f / (w10 * L1 + w11 * Lo1);
        __half* AO = g_aoh + (size_t)b * HWn * Cc;
        #pragma unroll
        for (int ct = 0; ct < 32; ct++) {
            int c = ct * 8 + t4 * 2;
            float2 o1a = *(const float2*)&OB[r0 * 260 + c];
            float2 o1b = *(const float2*)&OB[r1 * 260 + c];
            __half2 va = __floats2half2_rn((w00 * oacc[ct][0] + w01 * o1a.x) * inv0,
                                           (w00 * oacc[ct][1] + w01 * o1a.y) * inv0);
            __half2 vb2 = __floats2half2_rn((w10 * oacc[ct][2] + w11 * o1b.x) * inv1,
                                            (w10 * oacc[ct][3] + w11 * o1b.y) * inv1);
            *(__half2*)&AO[(size_t)(qbase + r0) * Cc + c] = va;
            *(__half2*)&AO[(size_t)(qbase + r1) * Cc + c] = vb2;
        }
    }
}

// ---------------- proj GEMM (fp16) + residual ------------------------------------
__global__ __launch_bounds__(256) void proj_kernel(const float* __restrict__ x,
                                                   const float* __restrict__ pb,
                                                   float* __restrict__ out) {
    extern __shared__ __align__(16) __half gsm[];
    int b = blockIdx.z;
    int om = blockIdx.y * 128;
    int pn = blockIdx.x * 128;
    const __half* Ag = g_pwh + (size_t)om * Cc;
    const __half* Bg = g_aoh + (size_t)b * HWn * Cc + (size_t)pn * Cc;

    float acc[2][8][4] = {};
    gemm16(Ag, Bg, gsm, acc);

    int t = threadIdx.x, wid = t >> 5, lane = t & 31, g = lane >> 2, t4 = lane & 3;
    int wm = (wid >> 1) * 32, wn = (wid & 1) * 64;

    #pragma unroll
    for (int mt = 0; mt < 2; mt++) {
        int o0 = om + wm + mt * 16 + g;
        float b0 = pb[o0], b1 = pb[o0 + 8];
        #pragma unroll
        for (int nt = 0; nt < 8; nt++) {
            int p0 = pn + wn + nt * 8 + t4 * 2;
            size_t off0 = ((size_t)b * Cc + o0) * HWn + p0;
            size_t off1 = ((size_t)b * Cc + o0 + 8) * HWn + p0;
            float2 x0 = *(const float2*)&x[off0];
            float2 x1 = *(const float2*)&x[off1];
            float2 v0 = { acc[mt][nt][0] + b0 + x0.x, acc[mt][nt][1] + b0 + x0.y };
            float2 v1 = { acc[mt][nt][2] + b1 + x1.x, acc[mt][nt][3] + b1 + x1.y };
            *(float2*)&out[off0] = v0;
            *(float2*)&out[off1] = v1;
        }
    }
}

// ---------------- launch ---------------------------------------------------------
extern "C" void kernel_launch(void* const* d_in, const int* in_sizes, int n_in,
                              void* d_out, int out_size) {
    const float* x  = (const float*)d_in[0];
    const float* nw = (const float*)d_in[1];
    const float* nb = (const float*)d_in[2];
    const float* qw = (const float*)d_in[3];
    const float* qb = (const float*)d_in[4];
    const float* pw = (const float*)d_in[5];
    const float* pb = (const float*)d_in[6];
    float* out = (float*)d_out;

    cudaFuncSetAttribute(flash_kernel, cudaFuncAttributeMaxDynamicSharedMemorySize,
                         SMEM_BYTES);
    cudaFuncSetAttribute(qkv_kernel, cudaFuncAttributeMaxDynamicSharedMemorySize,
                         GEMM_SMEM);
    cudaFuncSetAttribute(proj_kernel, cudaFuncAttributeMaxDynamicSharedMemorySize,
                         GEMM_SMEM);

    wconv_kernel<<<768, 256>>>(qw, pw);
    gn_kernel<<<Bn * 8, 512>>>(x, nw, nb);
    qkv_kernel<<<dim3(6, 32, 8), 256, GEMM_SMEM>>>(qb);
    flash_kernel<<<dim3(64, 8), 256, SMEM_BYTES>>>();
    proj_kernel<<<dim3(32, 2, 8), 256, GEMM_SMEM>>>(x, pb, out);
}

// round 10
// speedup vs baseline: 2.2058x; 1.0874x over previous
#include <cuda_runtime.h>
#include <cuda_fp16.h>
#include <cstdint>

#define Bn  8
#define Cc  256
#define HWn 4096

// ---- flash smem layout (half offsets) ----
#define QPH 264
#define VPH 72
#define PPH 72
#define OFF_Q  0
#define OFF_K0 16896
#define OFF_K1 33792
#define OFF_V0 50688
#define OFF_V1 69120
#define OFF_P0 87552
#define OFF_P1 92160
#define OFF_F  96768
// float region indices (base = smh + OFF_F): Fs[2][64] at 0, MX[2][64] at 128, Ls[2][64] at 256
#define F_MX 128
#define F_LS 256
#define SMEM_BYTES (OFF_F * 2 + 384 * 4)   // 195072 B

// ---- fp16 GEMM tiles (qkv/proj) ----
#define GP 264
#define GEMM_SMEM (2 * 128 * GP * 2)       // 135168 B

// ---------------- scratch -----------------------------------------------------
__device__ __half g_xnh[(size_t)Bn * HWn * Cc];
__device__ __half g_qwh[768 * 256];
__device__ __half g_pwh[256 * 256];
__device__ __half g_q [(size_t)Bn * HWn * Cc];
__device__ __half g_k [(size_t)Bn * HWn * Cc];
__device__ __half g_vt[(size_t)Bn * Cc * HWn];
__device__ __half g_aoh[(size_t)Bn * HWn * Cc];

// ---------------- helpers ------------------------------------------------------
__device__ __forceinline__ void mma16(float c[4], uint32_t a0, uint32_t a1, uint32_t a2,
                                      uint32_t a3, uint32_t b0, uint32_t b1) {
    asm("mma.sync.aligned.m16n8k16.row.col.f32.f16.f16.f32 "
        "{%0,%1,%2,%3},{%4,%5,%6,%7},{%8,%9},{%0,%1,%2,%3};"
        : "+f"(c[0]), "+f"(c[1]), "+f"(c[2]), "+f"(c[3])
        : "r"(a0), "r"(a1), "r"(a2), "r"(a3), "r"(b0), "r"(b1));
}
__device__ __forceinline__ void ldsm4(uint32_t& r0, uint32_t& r1, uint32_t& r2,
                                      uint32_t& r3, uint32_t a) {
    asm volatile("ldmatrix.sync.aligned.m8n8.x4.shared.b16 {%0,%1,%2,%3}, [%4];"
        : "=r"(r0), "=r"(r1), "=r"(r2), "=r"(r3) : "r"(a));
}
#define H2U(x) (*(const uint32_t*)&(x))

__device__ __forceinline__ void cp16(void* dst, const void* src) {
    uint32_t d = (uint32_t)__cvta_generic_to_shared(dst);
    asm volatile("cp.async.cg.shared.global [%0], [%1], 16;\n" :: "r"(d), "l"(src));
}
__device__ __forceinline__ void cpcommit() { asm volatile("cp.async.commit_group;\n"); }
template<int N> __device__ __forceinline__ void cpwait() {
    asm volatile("cp.async.wait_group %0;\n" :: "n"(N));
}

// ---------------- weight fp32 -> fp16 conversion --------------------------------
__global__ __launch_bounds__(256) void wconv_kernel(const float* __restrict__ qw,
                                                    const float* __restrict__ pw) {
    int i = blockIdx.x * 256 + threadIdx.x;
    if (i < 768 * 256) g_qwh[i] = __float2half(qw[i]);
    if (i < 256 * 256) g_pwh[i] = __float2half(pw[i]);
}

// ---------------- GroupNorm (fp16 out, token-major, smem transpose) --------------
__global__ __launch_bounds__(512) void gn_kernel(const float* __restrict__ x,
                                                 const float* __restrict__ w,
                                                 const float* __restrict__ bv) {
    __shared__ float sm[32][132];   // 132-float pitch: 528 B, 16B-aligned rows
    __shared__ float rs[16], rss[16], ws[32], bs[32];
    int bg = blockIdx.x, b = bg >> 3, g = bg & 7;
    const float* xb = x + ((size_t)b * Cc + (size_t)g * 32) * HWn;
    const int NEL = 32 * HWn;
    int tid = threadIdx.x;

    float s = 0.f, ss = 0.f;
    for (int i = tid; i < NEL; i += 512) {
        float v = xb[i];
        s += v; ss += v * v;
    }
    int lane = tid & 31, wid = tid >> 5;
    #pragma unroll
    for (int o = 16; o; o >>= 1) {
        s  += __shfl_down_sync(0xffffffffu, s, o);
        ss += __shfl_down_sync(0xffffffffu, ss, o);
    }
    if (lane == 0) { rs[wid] = s; rss[wid] = ss; }
    if (tid < 32) { ws[tid] = w[g * 32 + tid]; bs[tid] = bv[g * 32 + tid]; }
    __syncthreads();
    if (wid == 0) {
        s  = (lane < 16) ? rs[lane]  : 0.f;
        ss = (lane < 16) ? rss[lane] : 0.f;
        #pragma unroll
        for (int o = 8; o; o >>= 1) {
            s  += __shfl_down_sync(0xffffffffu, s, o);
            ss += __shfl_down_sync(0xffffffffu, ss, o);
        }
        if (lane == 0) { rs[0] = s; rss[0] = ss; }
    }
    __syncthreads();
    float mean = rs[0] / (float)NEL;
    float var  = rss[0] / (float)NEL - mean * mean;
    float rstd = rsqrtf(var + 1e-5f);

    __half* out = g_xnh + (size_t)b * HWn * Cc + g * 32;
    int c  = tid >> 4, pl = (tid & 15) * 8;
    int pl2 = tid >> 2, c8 = (tid & 3) * 8;

    for (int p0 = 0; p0 < HWn; p0 += 128) {
        float4 v0 = *(const float4*)(xb + (size_t)c * HWn + p0 + pl);
        float4 v1 = *(const float4*)(xb + (size_t)c * HWn + p0 + pl + 4);
        __syncthreads();
        *(float4*)&sm[c][pl]     = v0;
        *(float4*)&sm[c][pl + 4] = v1;
        __syncthreads();
        __half2 h[4];
        #pragma unroll
        for (int jj = 0; jj < 4; jj++) {
            int c0 = c8 + jj * 2;
            float a0 = (sm[c0][pl2]     - mean) * rstd * ws[c0]     + bs[c0];
            float a1 = (sm[c0 + 1][pl2] - mean) * rstd * ws[c0 + 1] + bs[c0 + 1];
            h[jj] = __floats2half2_rn(a0, a1);
        }
        *(uint4*)&out[(size_t)(p0 + pl2) * Cc + c8] = *(uint4*)h;
    }
}

// ---------------- fp16 NT GEMM core ----------------------------------------------
__device__ __forceinline__ void gemm16(const __half* __restrict__ Ag,
                                       const __half* __restrict__ Bg,
                                       __half* gsm, float acc[2][8][4]) {
    int t = threadIdx.x;
    #pragma unroll
    for (int i = 0; i < 16; i++) {
        int idx = t + 256 * i;
        int row = idx >> 5, pc = idx & 31;
        cp16(gsm + row * GP + pc * 8, Ag + (size_t)row * 256 + pc * 8);
        cp16(gsm + 128 * GP + row * GP + pc * 8, Bg + (size_t)row * 256 + pc * 8);
    }
    cpcommit();
    cpwait<0>();
    __syncthreads();

    int wid = t >> 5, lane = t & 31;
    int wm = (wid >> 1) * 32, wn = (wid & 1) * 64;
    uint32_t sb = (uint32_t)__cvta_generic_to_shared(gsm);
    uint32_t aA = sb + (uint32_t)((wm + (lane & 15)) * GP + (lane >> 4) * 8) * 2;
    uint32_t rowKV = (uint32_t)(((lane >> 4) << 3) + (lane & 7));
    uint32_t colHi = (uint32_t)(((lane >> 3) & 1) << 3);
    uint32_t aB = sb + (uint32_t)(128 * GP + (wn + rowKV) * GP + colHi) * 2;

    #pragma unroll
    for (int ks = 0; ks < 16; ks++) {
        uint32_t a[2][4];
        ldsm4(a[0][0], a[0][1], a[0][2], a[0][3], aA + ks * 32);
        ldsm4(a[1][0], a[1][1], a[1][2], a[1][3], aA + 16 * GP * 2 + ks * 32);
        #pragma unroll
        for (int ng = 0; ng < 4; ng++) {
            uint32_t b0, b1, b2, b3;
            ldsm4(b0, b1, b2, b3, aB + ng * (16 * GP * 2) + ks * 32);
            #pragma unroll
            for (int mt = 0; mt < 2; mt++) {
                mma16(acc[mt][ng * 2],     a[mt][0], a[mt][1], a[mt][2], a[mt][3], b0, b1);
                mma16(acc[mt][ng * 2 + 1], a[mt][0], a[mt][1], a[mt][2], a[mt][3], b2, b3);
            }
        }
    }
}

// ---------------- QKV GEMM ---------------------------------------------------------
__global__ __launch_bounds__(256) void qkv_kernel(const float* __restrict__ bias) {
    extern __shared__ __align__(16) __half gsm[];
    int b = blockIdx.z;
    int pm = blockIdx.y * 128;
    int on = blockIdx.x * 128;
    const __half* Ag = g_xnh + (size_t)b * HWn * Cc + (size_t)pm * Cc;
    const __half* Bg = g_qwh + (size_t)on * Cc;

    float acc[2][8][4] = {};
    gemm16(Ag, Bg, gsm, acc);

    int t = threadIdx.x, wid = t >> 5, lane = t & 31, g = lane >> 2, t4 = lane & 3;
    int wm = (wid >> 1) * 32, wn = (wid & 1) * 64;

    if (on < 512) {
        __half* dst = ((on < 256) ? g_q : g_k) + (size_t)b * HWn * Cc;
        int obase = on & 255;
        #pragma unroll
        for (int nt = 0; nt < 8; nt++) {
            int ocol = wn + nt * 8 + t4 * 2;
            float2 bb = *(const float2*)&bias[on + ocol];
            #pragma unroll
            for (int mt = 0; mt < 2; mt++) {
                int p0 = pm + wm + mt * 16 + g;
                __half2 v0 = __floats2half2_rn(acc[mt][nt][0] + bb.x, acc[mt][nt][1] + bb.y);
                __half2 v1 = __floats2half2_rn(acc[mt][nt][2] + bb.x, acc[mt][nt][3] + bb.y);
                *(__half2*)&dst[(size_t)p0 * Cc + obase + ocol]       = v0;
                *(__half2*)&dst[(size_t)(p0 + 8) * Cc + obase + ocol] = v1;
            }
        }
    } else {
        __half* dst = g_vt + (size_t)b * Cc * HWn;
        #pragma unroll
        for (int nt = 0; nt < 8; nt++) {
            int ocol = wn + nt * 8 + t4 * 2;
            int c0 = (on - 512) + ocol;
            float2 bb = *(const float2*)&bias[on + ocol];
            #pragma unroll
            for (int mt = 0; mt < 2; mt++) {
                int p0 = pm + wm + mt * 16 + g;
                dst[(size_t)c0 * HWn + p0]           = __float2half(acc[mt][nt][0] + bb.x);
                dst[(size_t)(c0 + 1) * HWn + p0]     = __float2half(acc[mt][nt][1] + bb.y);
                dst[(size_t)c0 * HWn + p0 + 8]       = __float2half(acc[mt][nt][2] + bb.x);
                dst[(size_t)(c0 + 1) * HWn + p0 + 8] = __float2half(acc[mt][nt][3] + bb.y);
            }
        }
    }
}

// ---------------- flash: warp-specialized producer/consumer ----------------------
__device__ __forceinline__ void copyK16(const __half* Kg, int kt, __half* kb, int t) {
    #pragma unroll
    for (int i = 0; i < 8; i++) {
        int idx = t + 256 * i;
        int row = idx >> 5, pc = idx & 31;
        cp16(kb + row * QPH + pc * 8, Kg + (size_t)(kt * 64 + row) * Cc + pc * 8);
    }
}
__device__ __forceinline__ void copyV16(const __half* Vtg, int kt, __half* vb, int t) {
    #pragma unroll
    for (int i = 0; i < 8; i++) {
        int idx = t + 256 * i;
        int c = idx >> 3, pc = idx & 7;
        cp16(vb + c * VPH + pc * 8, Vtg + (size_t)c * HWn + kt * 64 + pc * 8);
    }
}

__global__ void __launch_bounds__(512, 1) flash_kernel() {
    extern __shared__ __align__(16) __half smh[];
    float* smf = (float*)(smh + OFF_F);
    int b = blockIdx.y;
    int qbase = blockIdx.x * 64;
    const __half* Qg  = g_q  + (size_t)b * HWn * Cc + (size_t)qbase * Cc;
    const __half* Kg  = g_k  + (size_t)b * HWn * Cc;
    const __half* Vtg = g_vt + (size_t)b * Cc * HWn;

    int t = threadIdx.x;
    int wid = t >> 5, lane = t & 31, g = lane >> 2, t4 = lane & 3;
    bool isProd = (wid < 8);
    uint32_t sb = (uint32_t)__cvta_generic_to_shared(smh);
    uint32_t rowKV = (uint32_t)(((lane >> 4) << 3) + (lane & 7));
    uint32_t colHi = (uint32_t)(((lane >> 3) & 1) << 3);

    // producer identities
    int mi = (wid & 7) >> 1, ni = wid & 1;
    int wm = mi * 16;
    int r0 = wm + g, r1 = r0 + 8;
    uint32_t aQ  = sb + (uint32_t)(OFF_Q  + (wm + (lane & 15)) * QPH + (lane >> 4) * 8) * 2;
    uint32_t aK0 = sb + (uint32_t)(OFF_K0 + (ni * 32 + rowKV) * QPH + colHi) * 2;
    uint32_t aK1 = sb + (uint32_t)(OFF_K1 + (ni * 32 + rowKV) * QPH + colHi) * 2;

    // consumer identities
    int cw = wid - 8;
    int cq = (cw > 0 ? cw : 0) >> 1, cc = cw & 1;
    int cr0 = cq * 16 + g, cr1 = cr0 + 8;
    uint32_t aP0 = sb + (uint32_t)(OFF_P0 + (cq * 16 + (lane & 15)) * PPH + (lane >> 4) * 8) * 2;
    uint32_t aP1 = sb + (uint32_t)(OFF_P1 + (cq * 16 + (lane & 15)) * PPH + (lane >> 4) * 8) * 2;
    uint32_t aV0 = sb + (uint32_t)(OFF_V0 + (cc * 128 + rowKV) * VPH + colHi) * 2;
    uint32_t aV1 = sb + (uint32_t)(OFF_V1 + (cc * 128 + rowKV) * VPH + colHi) * 2;

    float oacc[16][4] = {};
    float M0 = -1e30f, M1 = -1e30f, L0 = 0.f, L1 = 0.f;

    // prologue: producers copy K(0); consumers copy Q
    if (isProd) copyK16(Kg, 0, smh + OFF_K0, t);
    else        copyK16(Qg, 0, smh + OFF_Q, t - 256);   // Q has identical shape/pitch
    cpcommit();
    cpwait<0>();
    __syncthreads();

    const float SCL = 0.09016844f;   // log2(e)/16

    for (int i = 0; i <= 64; i++) {
        if (isProd) {
            if (i < 63) {
                copyK16(Kg, i + 1, smh + (((i + 1) & 1) ? OFF_K1 : OFF_K0), t);
                cpcommit();
            }
            if (i < 64) {
                // ---- S(i) = Q K(i)^T, warp-local 16q x 32m ----
                uint32_t kb = (i & 1) ? aK1 : aK0;
                float sacc[4][4] = {};
                #pragma unroll
                for (int ks = 0; ks < 16; ks++) {
                    uint32_t q0, q1, q2, q3;
                    ldsm4(q0, q1, q2, q3, aQ + ks * 32);
                    #pragma unroll
                    for (int ntp = 0; ntp < 2; ntp++) {
                        uint32_t b0, b1, b2, b3;
                        ldsm4(b0, b1, b2, b3, kb + ntp * (16 * QPH * 2) + ks * 32);
                        mma16(sacc[ntp * 2],     q0, q1, q2, q3, b0, b1);
                        mma16(sacc[ntp * 2 + 1], q0, q1, q2, q3, b2, b3);
                    }
                }
                // ---- softmax with cross-half max ----
                float mx0 = -1e30f, mx1 = -1e30f;
                #pragma unroll
                for (int nt = 0; nt < 4; nt++) {
                    #pragma unroll
                    for (int jj = 0; jj < 4; jj++) sacc[nt][jj] *= SCL;
                    mx0 = fmaxf(mx0, fmaxf(sacc[nt][0], sacc[nt][1]));
                    mx1 = fmaxf(mx1, fmaxf(sacc[nt][2], sacc[nt][3]));
                }
                mx0 = fmaxf(mx0, __shfl_xor_sync(0xffffffffu, mx0, 1));
                mx0 = fmaxf(mx0, __shfl_xor_sync(0xffffffffu, mx0, 2));
                mx1 = fmaxf(mx1, __shfl_xor_sync(0xffffffffu, mx1, 1));
                mx1 = fmaxf(mx1, __shfl_xor_sync(0xffffffffu, mx1, 2));
                if (t4 == 0) {
                    smf[F_MX + ni * 64 + r0] = mx0;
                    smf[F_MX + ni * 64 + r1] = mx1;
                }
                asm volatile("bar.sync 1, 256;" ::: "memory");
                float Mn0 = fmaxf(M0, fmaxf(mx0, smf[F_MX + (1 - ni) * 64 + r0]));
                float Mn1 = fmaxf(M1, fmaxf(mx1, smf[F_MX + (1 - ni) * 64 + r1]));
                float f0 = exp2f(M0 - Mn0), f1 = exp2f(M1 - Mn1);
                M0 = Mn0; M1 = Mn1;
                if (ni == 0 && t4 == 0) {
                    smf[(i & 1) * 64 + r0] = f0;
                    smf[(i & 1) * 64 + r1] = f1;
                }
                // ---- P(i), L ----
                float s0 = 0.f, s1 = 0.f;
                __half* Pb = smh + ((i & 1) ? OFF_P1 : OFF_P0);
                #pragma unroll
                for (int nt = 0; nt < 4; nt++) {
                    float p00 = exp2f(sacc[nt][0] - Mn0);
                    float p01 = exp2f(sacc[nt][1] - Mn0);
                    float p10 = exp2f(sacc[nt][2] - Mn1);
                    float p11 = exp2f(sacc[nt][3] - Mn1);
                    s0 += p00 + p01; s1 += p10 + p11;
                    __half2 u0 = __floats2half2_rn(p00, p01);
                    __half2 u1 = __floats2half2_rn(p10, p11);
                    int ccol = ni * 32 + nt * 8 + t4 * 2;
                    *(__half2*)&Pb[r0 * PPH + ccol] = u0;
                    *(__half2*)&Pb[r1 * PPH + ccol] = u1;
                }
                s0 += __shfl_xor_sync(0xffffffffu, s0, 1);
                s0 += __shfl_xor_sync(0xffffffffu, s0, 2);
                s1 += __shfl_xor_sync(0xffffffffu, s1, 1);
                s1 += __shfl_xor_sync(0xffffffffu, s1, 2);
                L0 = L0 * f0 + s0;
                L1 = L1 * f1 + s1;
            } else {
                // i == 64: publish L halves
                if (t4 == 0) {
                    smf[F_LS + ni * 64 + r0] = L0;
                    smf[F_LS + ni * 64 + r1] = L1;
                }
            }
        } else {
            if (i < 64) {
                copyV16(Vtg, i, smh + ((i & 1) ? OFF_V1 : OFF_V0), t - 256);
                cpcommit();
            }
            if (i >= 1) {
                int j = i - 1;
                float f0 = smf[(j & 1) * 64 + cr0];
                float f1 = smf[(j & 1) * 64 + cr1];
                bool nor = (f0 == 1.f) && (f1 == 1.f);
                if (__ballot_sync(0xffffffffu, nor) != 0xffffffffu) {
                    #pragma unroll
                    for (int q = 0; q < 16; q++) {
                        oacc[q][0] *= f0; oacc[q][1] *= f0;
                        oacc[q][2] *= f1; oacc[q][3] *= f1;
                    }
                }
                uint32_t aP = (j & 1) ? aP1 : aP0;
                uint32_t aV = (j & 1) ? aV1 : aV0;
                #pragma unroll
                for (int km = 0; km < 4; km++) {
                    uint32_t pa0, pa1, pa2, pa3;
                    ldsm4(pa0, pa1, pa2, pa3, aP + km * 32);
                    #pragma unroll
                    for (int ct = 0; ct < 8; ct++) {
                        uint32_t v0, v1, v2, v3;
                        ldsm4(v0, v1, v2, v3, aV + ct * (16 * VPH * 2) + km * 32);
                        mma16(oacc[ct * 2],     pa0, pa1, pa2, pa3, v0, v1);
                        mma16(oacc[ct * 2 + 1], pa0, pa1, pa2, pa3, v2, v3);
                    }
                }
            }
        }
        cpwait<0>();
        __syncthreads();
    }

    // epilogue: consumers normalize and store fp16 ao
    if (!isProd) {
        float Lt0 = smf[F_LS + cr0] + smf[F_LS + 64 + cr0];
        float Lt1 = smf[F_LS + cr1] + smf[F_LS + 64 + cr1];
        float inv0 = 1.0f / Lt0, inv1 = 1.0f / Lt1;
        __half* AO = g_aoh + (size_t)b * HWn * Cc;
        #pragma unroll
        for (int q = 0; q < 16; q++) {
            int ch = cc * 128 + q * 8 + t4 * 2;
            __half2 v0 = __floats2half2_rn(oacc[q][0] * inv0, oacc[q][1] * inv0);
            __half2 v1 = __floats2half2_rn(oacc[q][2] * inv1, oacc[q][3] * inv1);
            *(__half2*)&AO[(size_t)(qbase + cr0) * Cc + ch] = v0;
            *(__half2*)&AO[(size_t)(qbase + cr1) * Cc + ch] = v1;
        }
    }
}

// ---------------- proj GEMM (fp16) + residual ------------------------------------
__global__ __launch_bounds__(256) void proj_kernel(const float* __restrict__ x,
                                                   const float* __restrict__ pb,
                                                   float* __restrict__ out) {
    extern __shared__ __align__(16) __half gsm[];
    int b = blockIdx.z;
    int om = blockIdx.y * 128;
    int pn = blockIdx.x * 128;
    const __half* Ag = g_pwh + (size_t)om * Cc;
    const __half* Bg = g_aoh + (size_t)b * HWn * Cc + (size_t)pn * Cc;

    float acc[2][8][4] = {};
    gemm16(Ag, Bg, gsm, acc);

    int t = threadIdx.x, wid = t >> 5, lane = t & 31, g = lane >> 2, t4 = lane & 3;
    int wm = (wid >> 1) * 32, wn = (wid & 1) * 64;

    #pragma unroll
    for (int mt = 0; mt < 2; mt++) {
        int o0 = om + wm + mt * 16 + g;
        float b0 = pb[o0], b1 = pb[o0 + 8];
        #pragma unroll
        for (int nt = 0; nt < 8; nt++) {
            int p0 = pn + wn + nt * 8 + t4 * 2;
            size_t off0 = ((size_t)b * Cc + o0) * HWn + p0;
            size_t off1 = ((size_t)b * Cc + o0 + 8) * HWn + p0;
            float2 x0 = *(const float2*)&x[off0];
            float2 x1 = *(const float2*)&x[off1];
            float2 v0 = { acc[mt][nt][0] + b0 + x0.x, acc[mt][nt][1] + b0 + x0.y };
            float2 v1 = { acc[mt][nt][2] + b1 + x1.x, acc[mt][nt][3] + b1 + x1.y };
            *(float2*)&out[off0] = v0;
            *(float2*)&out[off1] = v1;
        }
    }
}

// ---------------- launch ---------------------------------------------------------
extern "C" void kernel_launch(void* const* d_in, const int* in_sizes, int n_in,
                              void* d_out, int out_size) {
    const float* x  = (const float*)d_in[0];
    const float* nw = (const float*)d_in[1];
    const float* nb = (const float*)d_in[2];
    const float* qw = (const float*)d_in[3];
    const float* qb = (const float*)d_in[4];
    const float* pw = (const float*)d_in[5];
    const float* pb = (const float*)d_in[6];
    float* out = (float*)d_out;

    cudaFuncSetAttribute(flash_kernel, cudaFuncAttributeMaxDynamicSharedMemorySize,
                         SMEM_BYTES);
    cudaFuncSetAttribute(qkv_kernel, cudaFuncAttributeMaxDynamicSharedMemorySize,
                         GEMM_SMEM);
    cudaFuncSetAttribute(proj_kernel, cudaFuncAttributeMaxDynamicSharedMemorySize,
                         GEMM_SMEM);

    wconv_kernel<<<768, 256>>>(qw, pw);
    gn_kernel<<<Bn * 8, 512>>>(x, nw, nb);
    qkv_kernel<<<dim3(6, 32, 8), 256, GEMM_SMEM>>>(qb);
    flash_kernel<<<dim3(64, 8), 512, SMEM_BYTES>>>();
    proj_kernel<<<dim3(32, 2, 8), 256, GEMM_SMEM>>>(x, pb, out);
}